// round 1
// baseline (speedup 1.0000x reference)
#include <cuda_runtime.h>
#include <cuda_bf16.h>
#include <math.h>

// Problem constants (fixed by setup_inputs)
#define T_MAX 4096
#define D_MODEL 1280
#define NHEAD 16
#define HD 80
#define E3 (3 * D_MODEL)   // 3840
#define WIN 64

// ---------------------------------------------------------------------------
// Scratch (device globals; no allocations allowed)
// ---------------------------------------------------------------------------
__device__ float g_qkv[T_MAX * E3];               // 62.9 MB
__device__ float g_q[NHEAD * T_MAX * HD];         // 21 MB
__device__ float g_k[NHEAD * T_MAX * HD];         // 21 MB
__device__ float g_v[NHEAD * T_MAX * HD];         // 21 MB
__device__ float g_att[T_MAX * D_MODEL];          // 21 MB

// ---------------------------------------------------------------------------
// Kernel 1/4: SGEMM with bias.  C[M,N] = A[M,K] @ B[K,N] + bias[N]
// BM=BN=128, BK=8, TM=TN=8, 256 threads. All dims are multiples, no guards.
// ---------------------------------------------------------------------------
__global__ void __launch_bounds__(256, 2)
sgemm_bias_kernel(int M, int N, int K,
                  const float* __restrict__ A,
                  const float* __restrict__ B,
                  const float* __restrict__ bias,
                  float* __restrict__ C)
{
    const int BM = 128, BN = 128, BK = 8, TM = 8, TN = 8;
    __shared__ float As[BK * BM];   // transposed A tile
    __shared__ float Bs[BK * BN];

    int tid = threadIdx.x;
    int brow = blockIdx.y;
    int bcol = blockIdx.x;

    const float* Ablk = A + (size_t)brow * BM * K;
    const float* Bblk = B + (size_t)bcol * BN;
    float* Cblk = C + (size_t)brow * BM * N + bcol * BN;

    int innerRowA = tid >> 1;        // 0..127
    int innerColA = (tid & 1) * 4;   // 0 or 4
    int innerRowB = tid >> 5;        // 0..7
    int innerColB = (tid & 31) * 4;  // 0..124

    int threadRow = tid >> 4;        // 0..15
    int threadCol = tid & 15;        // 0..15

    float acc[TM][TN];
    #pragma unroll
    for (int i = 0; i < TM; ++i)
        #pragma unroll
        for (int j = 0; j < TN; ++j) acc[i][j] = 0.f;

    float regM[TM], regN[TN];

    for (int k0 = 0; k0 < K; k0 += BK) {
        float4 a4 = *reinterpret_cast<const float4*>(Ablk + (size_t)innerRowA * K + k0 + innerColA);
        As[(innerColA + 0) * BM + innerRowA] = a4.x;
        As[(innerColA + 1) * BM + innerRowA] = a4.y;
        As[(innerColA + 2) * BM + innerRowA] = a4.z;
        As[(innerColA + 3) * BM + innerRowA] = a4.w;
        float4 b4 = *reinterpret_cast<const float4*>(Bblk + (size_t)(k0 + innerRowB) * N + innerColB);
        *reinterpret_cast<float4*>(&Bs[innerRowB * BN + innerColB]) = b4;
        __syncthreads();

        #pragma unroll
        for (int kk = 0; kk < BK; ++kk) {
            #pragma unroll
            for (int i = 0; i < TM; ++i) regM[i] = As[kk * BM + threadRow * TM + i];
            #pragma unroll
            for (int j = 0; j < TN; ++j) regN[j] = Bs[kk * BN + threadCol * TN + j];
            #pragma unroll
            for (int i = 0; i < TM; ++i)
                #pragma unroll
                for (int j = 0; j < TN; ++j)
                    acc[i][j] += regM[i] * regN[j];
        }
        __syncthreads();
    }

    #pragma unroll
    for (int i = 0; i < TM; ++i) {
        int row = threadRow * TM + i;
        #pragma unroll
        for (int j = 0; j < TN; j += 4) {
            int col = threadCol * TN + j;
            int gcol = bcol * BN + col;
            float4 o;
            o.x = acc[i][j + 0] + bias[gcol + 0];
            o.y = acc[i][j + 1] + bias[gcol + 1];
            o.z = acc[i][j + 2] + bias[gcol + 2];
            o.w = acc[i][j + 3] + bias[gcol + 3];
            *reinterpret_cast<float4*>(&Cblk[(size_t)row * N + col]) = o;
        }
    }
}

// ---------------------------------------------------------------------------
// Kernel 2: RoPE + split qkv into per-head layout [H][T][HD]
// ---------------------------------------------------------------------------
__global__ void rope_split_kernel(const float* __restrict__ rope, int T)
{
    int idx = blockIdx.x * blockDim.x + threadIdx.x;
    int total = T * NHEAD * HD;
    if (idx >= total) return;
    int d = idx % HD;
    int th = idx / HD;
    int h = th % NHEAD;
    int t = th / NHEAD;

    size_t base = (size_t)t * E3 + h * HD;
    float qv, kv;
    if (d < HD / 2) {
        float ang = rope[t * (HD / 2) + d];
        float c = cosf(ang), s = sinf(ang);
        float qr = g_qkv[base + d],           qi = g_qkv[base + d + HD / 2];
        float kr = g_qkv[base + D_MODEL + d], ki = g_qkv[base + D_MODEL + d + HD / 2];
        qv = qr * c - qi * s;
        kv = kr * c - ki * s;
    } else {
        int j = d - HD / 2;
        float ang = rope[t * (HD / 2) + j];
        float c = cosf(ang), s = sinf(ang);
        float qr = g_qkv[base + j],           qi = g_qkv[base + d];
        float kr = g_qkv[base + D_MODEL + j], ki = g_qkv[base + D_MODEL + d];
        qv = qr * s + qi * c;
        kv = kr * s + ki * c;
    }
    size_t o = (size_t)h * T * HD + (size_t)t * HD + d;
    g_q[o] = qv;
    g_k[o] = kv;
    g_v[o] = g_qkv[base + 2 * D_MODEL + d];
}

// ---------------------------------------------------------------------------
// Kernel 3: windowed causal attention. One block per (segment, head).
// Assumes segment length <= 64 (windows are exactly 64 in this problem).
// Dynamic smem: Qs[64*80] + Ks[64*81] + Vs[64*80] + S[64*64] floats = 78080 B
// ---------------------------------------------------------------------------
__global__ void attn_kernel(const int* __restrict__ cu, int T, float* __restrict__ attn_out)
{
    extern __shared__ float sm[];
    float* Qs = sm;                       // [64][80]
    float* Ks = Qs + WIN * HD;            // [64][81]  padded -> conflict free
    float* Vs = Ks + WIN * 81;            // [64][80]
    float* S  = Vs + WIN * HD;            // [64][64]  logits then probs

    int seg = blockIdx.x;
    int h   = blockIdx.y;
    int st  = cu[seg];
    int en  = cu[seg + 1];
    int L   = en - st;
    if (L > WIN) L = WIN;   // problem guarantees 64
    int tid = threadIdx.x;  // 128 threads
    const float scale = 0.11180339887498948f;  // 1/sqrt(80)

    const float* Qg = g_q + (size_t)h * T * HD;
    const float* Kg = g_k + (size_t)h * T * HD;
    const float* Vg = g_v + (size_t)h * T * HD;

    // load tiles
    for (int e = tid; e < WIN * HD; e += blockDim.x) {
        int r = e / HD, d = e % HD;
        float qv = 0.f, kv = 0.f, vv = 0.f;
        if (r < L) {
            size_t g = (size_t)(st + r) * HD + d;
            qv = Qg[g]; kv = Kg[g]; vv = Vg[g];
        }
        Qs[r * HD + d] = qv;
        Ks[r * 81 + d] = kv;
        Vs[r * HD + d] = vv;
    }
    __syncthreads();

    // logits (causal, within segment)
    for (int e = tid; e < WIN * WIN; e += blockDim.x) {
        int r = e >> 6, c = e & 63;
        if (r < L && c <= r) {
            float acc = 0.f;
            #pragma unroll 8
            for (int d = 0; d < HD; ++d)
                acc += Qs[r * HD + d] * Ks[c * 81 + d];
            S[e] = acc * scale;
        }
    }
    __syncthreads();

    // softmax, one thread per row
    if (tid < WIN) {
        int r = tid;
        if (r < L) {
            float m = -1e30f;
            for (int c = 0; c <= r; ++c) m = fmaxf(m, S[r * WIN + c]);
            float sum = 0.f;
            for (int c = 0; c <= r; ++c) {
                float e = expf(S[r * WIN + c] - m);
                S[r * WIN + c] = e;
                sum += e;
            }
            float inv = 1.f / sum;
            for (int c = 0; c < WIN; ++c)
                S[r * WIN + c] = (c <= r) ? S[r * WIN + c] * inv : 0.f;
        } else {
            for (int c = 0; c < WIN; ++c) S[r * WIN + c] = 0.f;
        }
    }
    __syncthreads();

    // O = P @ V, write into [T][D] layout
    for (int e = tid; e < WIN * HD; e += blockDim.x) {
        int r = e / HD, d = e % HD;
        if (r >= L) continue;
        float acc = 0.f;
        #pragma unroll 8
        for (int c = 0; c < WIN; ++c)
            acc += S[r * WIN + c] * Vs[c * HD + d];
        attn_out[(size_t)(st + r) * D_MODEL + h * HD + d] = acc;
    }
}

// ---------------------------------------------------------------------------
// launch
// ---------------------------------------------------------------------------
extern "C" void kernel_launch(void* const* d_in, const int* in_sizes, int n_in,
                              void* d_out, int out_size)
{
    const float* x    = (const float*)d_in[0];
    const float* rope = (const float*)d_in[1];
    const int*   cu   = (const int*)  d_in[2];
    const float* Wqkv = (const float*)d_in[3];
    const float* bqkv = (const float*)d_in[4];
    const float* Wo   = (const float*)d_in[5];
    const float* bo   = (const float*)d_in[6];
    float* out = (float*)d_out;

    const int T = in_sizes[0] / D_MODEL;   // 4096 (B=1)
    const int nseg = in_sizes[2] - 1;      // 64

    float *qkv_p, *att_p;
    cudaGetSymbolAddress((void**)&qkv_p, g_qkv);
    cudaGetSymbolAddress((void**)&att_p, g_att);

    // 1) QKV projection: [T,1280] @ [1280,3840] + b
    {
        dim3 grid(E3 / 128, T / 128);
        sgemm_bias_kernel<<<grid, 256>>>(T, E3, D_MODEL, x, Wqkv, bqkv, qkv_p);
    }

    // 2) RoPE + head split
    {
        int total = T * NHEAD * HD;
        rope_split_kernel<<<(total + 255) / 256, 256>>>(rope, T);
    }

    // 3) windowed attention
    {
        int smem = (WIN * HD + WIN * 81 + WIN * HD + WIN * WIN) * (int)sizeof(float);
        cudaFuncSetAttribute(attn_kernel, cudaFuncAttributeMaxDynamicSharedMemorySize, smem);
        dim3 grid(nseg, NHEAD);
        attn_kernel<<<grid, 128, smem>>>(cu, T, att_p);
    }

    // 4) output projection: [T,1280] @ [1280,1280] + b
    {
        dim3 grid(D_MODEL / 128, T / 128);
        sgemm_bias_kernel<<<grid, 256>>>(T, D_MODEL, D_MODEL, att_p, Wo, bo, out);
    }
}

// round 5
// speedup vs baseline: 1.9829x; 1.9829x over previous
#include <cuda_runtime.h>
#include <cuda_bf16.h>
#include <math.h>
#include <stdint.h>

// Problem constants (fixed by setup_inputs)
#define T_MAX 4096
#define D_MODEL 1280
#define NHEAD 16
#define HD 80
#define E3 (3 * D_MODEL)   // 3840
#define WIN 64
#define KDIM 1280

// ---------------------------------------------------------------------------
// Scratch (device globals; no allocations allowed)
// ---------------------------------------------------------------------------
__device__ float g_qkv[T_MAX * E3];
__device__ float g_q[NHEAD * T_MAX * HD];
__device__ float g_k[NHEAD * T_MAX * HD];
__device__ float g_v[NHEAD * T_MAX * HD];
__device__ float g_att[T_MAX * D_MODEL];

__device__ __nv_bfloat16 g_xh[T_MAX * D_MODEL];
__device__ __nv_bfloat16 g_xl[T_MAX * D_MODEL];
__device__ __nv_bfloat16 g_wqh[E3 * D_MODEL];     // Wqkv^T [N,K]
__device__ __nv_bfloat16 g_wql[E3 * D_MODEL];
__device__ __nv_bfloat16 g_woh[D_MODEL * D_MODEL];
__device__ __nv_bfloat16 g_wol[D_MODEL * D_MODEL];
__device__ __nv_bfloat16 g_ah[T_MAX * D_MODEL];
__device__ __nv_bfloat16 g_al[T_MAX * D_MODEL];

// ---------------------------------------------------------------------------
// Low-level helpers (all baseline PTX: sm_80-era, safe for compute_100)
// ---------------------------------------------------------------------------
__device__ __forceinline__ uint32_t smem_u32(const void* p) {
    uint32_t a;
    asm("{ .reg .u64 t; cvta.to.shared.u64 t, %1; cvt.u32.u64 %0, t; }"
        : "=r"(a) : "l"(p));
    return a;
}

__device__ __forceinline__ void cp_async16(uint32_t dst, const void* src) {
    asm volatile("cp.async.cg.shared.global [%0], [%1], 16;" :: "r"(dst), "l"(src));
}

__device__ __forceinline__ void ldm_x4(uint32_t* r, uint32_t addr) {
    asm volatile("ldmatrix.sync.aligned.m8n8.x4.shared.b16 {%0,%1,%2,%3}, [%4];"
                 : "=r"(r[0]), "=r"(r[1]), "=r"(r[2]), "=r"(r[3]) : "r"(addr));
}

__device__ __forceinline__ void mma_bf16(float* d, const uint32_t* a, const uint32_t* b) {
    asm volatile(
        "mma.sync.aligned.m16n8k16.row.col.f32.bf16.bf16.f32 "
        "{%0,%1,%2,%3}, {%4,%5,%6,%7}, {%8,%9}, {%0,%1,%2,%3};"
        : "+f"(d[0]), "+f"(d[1]), "+f"(d[2]), "+f"(d[3])
        : "r"(a[0]), "r"(a[1]), "r"(a[2]), "r"(a[3]), "r"(b[0]), "r"(b[1]));
}

// ---------------------------------------------------------------------------
// GEMM: C[M,N] = (Ah+Al)[M,K] @ (Bh+Bl)[N,K]^T + bias[N]  (fp32 accum)
// mma.sync bf16, 128x128 tile, BK=32, 3-stage cp.async pipeline.
// smem row stride = 40 bf16 (80B): conflict-free for ldmatrix (phase 5r mod 8).
// ---------------------------------------------------------------------------
#define GBM 128
#define GBN 128
#define GBK 32
#define ROWP 40                        // padded row length (elements)
#define TILE_B (128 * ROWP * 2)        // 10240 bytes per sub-tile
#define STAGE_B (4 * TILE_B)           // Ah, Al, Bh, Bl = 40960 bytes
#define NSTAGE 3

__global__ void __launch_bounds__(256, 1)
gemm_bf16x3(int M, int N, int K,
            const __nv_bfloat16* __restrict__ Ah, const __nv_bfloat16* __restrict__ Al,
            const __nv_bfloat16* __restrict__ Bh, const __nv_bfloat16* __restrict__ Bl,
            const float* __restrict__ bias, float* __restrict__ C)
{
    extern __shared__ __align__(128) char dsm[];
    const uint32_t sbase = smem_u32(dsm);

    const int tid  = threadIdx.x;
    const int wid  = tid >> 5;
    const int lane = tid & 31;
    const int warp_m = wid >> 2;       // 0..1
    const int warp_n = wid & 3;        // 0..3
    const int m0 = blockIdx.y * GBM;
    const int n0 = blockIdx.x * GBN;

    const int NC = K / GBK;

    // ---- stage loader -----------------------------------------------------
    auto load_stage = [&](int cidx) {
        const uint32_t sb = sbase + (uint32_t)(cidx % NSTAGE) * STAGE_B;
        const int k0 = cidx * GBK;
        const __nv_bfloat16* srcs[4] = {
            Ah + (size_t)m0 * K + k0,
            Al + (size_t)m0 * K + k0,
            Bh + (size_t)n0 * K + k0,
            Bl + (size_t)n0 * K + k0
        };
        #pragma unroll
        for (int t = 0; t < 4; ++t) {
            const __nv_bfloat16* sp = srcs[t];
            #pragma unroll
            for (int j = 0; j < 2; ++j) {
                int e   = tid + j * 256;       // 0..511
                int row = e >> 2;              // 0..127
                int ch  = e & 3;               // 16B chunk within 64B row
                cp_async16(sb + (uint32_t)t * TILE_B + (uint32_t)(row * 80 + ch * 16),
                           sp + (size_t)row * K + ch * 8);
            }
        }
        asm volatile("cp.async.commit_group;");
    };

    float acc[4][4][4];
    #pragma unroll
    for (int i = 0; i < 4; ++i)
        #pragma unroll
        for (int j = 0; j < 4; ++j)
            #pragma unroll
            for (int q = 0; q < 4; ++q) acc[i][j][q] = 0.f;

    // prologue: stages 0 and 1 in flight
    load_stage(0);
    load_stage(1);

    // ldmatrix lane addressing (fixed per thread)
    const int a_row = lane & 15;
    const int a_kof = (lane >> 4) * 8;
    const int b_row = (lane & 7) + ((lane >> 4) << 3);
    const int b_kof = ((lane >> 3) & 1) * 8;

    for (int c = 0; c < NC; ++c) {
        if (c + 2 < NC) {
            load_stage(c + 2);
            asm volatile("cp.async.wait_group 2;");
        } else if (c + 1 < NC) {
            asm volatile("cp.async.wait_group 1;");
        } else {
            asm volatile("cp.async.wait_group 0;");
        }
        __syncthreads();

        const uint32_t sb = sbase + (uint32_t)(c % NSTAGE) * STAGE_B;

        #pragma unroll
        for (int kk = 0; kk < 2; ++kk) {
            const int k0 = kk * 16;
            uint32_t aH[4][4], aL[4][4], bH[2][4], bL[2][4];
            #pragma unroll
            for (int ma = 0; ma < 4; ++ma) {
                int row = warp_m * 64 + ma * 16 + a_row;
                uint32_t off = (uint32_t)(row * ROWP + k0 + a_kof) * 2;
                ldm_x4(aH[ma], sb + 0 * TILE_B + off);
                ldm_x4(aL[ma], sb + 1 * TILE_B + off);
            }
            #pragma unroll
            for (int np = 0; np < 2; ++np) {
                int row = warp_n * 32 + np * 16 + b_row;
                uint32_t off = (uint32_t)(row * ROWP + k0 + b_kof) * 2;
                ldm_x4(bH[np], sb + 2 * TILE_B + off);
                ldm_x4(bL[np], sb + 3 * TILE_B + off);
            }
            #pragma unroll
            for (int ma = 0; ma < 4; ++ma) {
                #pragma unroll
                for (int nb = 0; nb < 4; ++nb) {
                    const uint32_t* bh = &bH[nb >> 1][(nb & 1) * 2];
                    const uint32_t* bl = &bL[nb >> 1][(nb & 1) * 2];
                    mma_bf16(acc[ma][nb], aH[ma], bh);
                    mma_bf16(acc[ma][nb], aH[ma], bl);
                    mma_bf16(acc[ma][nb], aL[ma], bh);
                }
            }
        }
        __syncthreads();
    }

    // ---- epilogue: direct stores with bias --------------------------------
    const int er = lane >> 2;          // 0..7
    const int ec = (lane & 3) * 2;     // 0,2,4,6
    #pragma unroll
    for (int ma = 0; ma < 4; ++ma) {
        int gr = m0 + warp_m * 64 + ma * 16 + er;
        #pragma unroll
        for (int nb = 0; nb < 4; ++nb) {
            int gc = n0 + warp_n * 32 + nb * 8 + ec;
            float b0 = __ldg(&bias[gc]);
            float b1 = __ldg(&bias[gc + 1]);
            float2 v0 = make_float2(acc[ma][nb][0] + b0, acc[ma][nb][1] + b1);
            float2 v1 = make_float2(acc[ma][nb][2] + b0, acc[ma][nb][3] + b1);
            *(float2*)&C[(size_t)gr * N + gc] = v0;
            *(float2*)&C[(size_t)(gr + 8) * N + gc] = v1;
        }
    }
}

// ---------------------------------------------------------------------------
// Split fp32 -> bf16 hi/lo
// ---------------------------------------------------------------------------
__global__ void split_bf16_kernel(const float* __restrict__ x,
                                  __nv_bfloat16* __restrict__ h,
                                  __nv_bfloat16* __restrict__ l, int n)
{
    int i = blockIdx.x * blockDim.x + threadIdx.x;
    if (i < n) {
        float v = x[i];
        __nv_bfloat16 hi = __float2bfloat16_rn(v);
        h[i] = hi;
        l[i] = __float2bfloat16_rn(v - __bfloat162float(hi));
    }
}

// ---------------------------------------------------------------------------
// Transpose + split: W[K,N] fp32 -> Wt_h, Wt_l [N,K] bf16
// ---------------------------------------------------------------------------
__global__ void transpose_split_kernel(const float* __restrict__ W,
                                       __nv_bfloat16* __restrict__ th,
                                       __nv_bfloat16* __restrict__ tl,
                                       int Kd, int Nd)
{
    __shared__ float tile[32][33];
    int kb = blockIdx.y * 32, nb = blockIdx.x * 32;
    int tx = threadIdx.x, ty = threadIdx.y;    // 32 x 8
    #pragma unroll
    for (int i = 0; i < 32; i += 8)
        tile[ty + i][tx] = W[(size_t)(kb + ty + i) * Nd + nb + tx];
    __syncthreads();
    #pragma unroll
    for (int i = 0; i < 32; i += 8) {
        float v = tile[tx][ty + i];
        __nv_bfloat16 hi = __float2bfloat16_rn(v);
        size_t o = (size_t)(nb + ty + i) * Kd + kb + tx;
        th[o] = hi;
        tl[o] = __float2bfloat16_rn(v - __bfloat162float(hi));
    }
}

// ---------------------------------------------------------------------------
// RoPE + split qkv into per-head layout [H][T][HD]
// ---------------------------------------------------------------------------
__global__ void rope_split_kernel(const float* __restrict__ rope, int T)
{
    int idx = blockIdx.x * blockDim.x + threadIdx.x;
    int total = T * NHEAD * HD;
    if (idx >= total) return;
    int d = idx % HD;
    int th = idx / HD;
    int h = th % NHEAD;
    int t = th / NHEAD;

    size_t base = (size_t)t * E3 + h * HD;
    float qv, kv;
    if (d < HD / 2) {
        float ang = rope[t * (HD / 2) + d];
        float c = cosf(ang), s = sinf(ang);
        float qr = g_qkv[base + d],           qi = g_qkv[base + d + HD / 2];
        float kr = g_qkv[base + D_MODEL + d], ki = g_qkv[base + D_MODEL + d + HD / 2];
        qv = qr * c - qi * s;
        kv = kr * c - ki * s;
    } else {
        int j = d - HD / 2;
        float ang = rope[t * (HD / 2) + j];
        float c = cosf(ang), s = sinf(ang);
        float qr = g_qkv[base + j],           qi = g_qkv[base + d];
        float kr = g_qkv[base + D_MODEL + j], ki = g_qkv[base + D_MODEL + d];
        qv = qr * s + qi * c;
        kv = kr * s + ki * c;
    }
    size_t o = (size_t)h * T * HD + (size_t)t * HD + d;
    g_q[o] = qv;
    g_k[o] = kv;
    g_v[o] = g_qkv[base + 2 * D_MODEL + d];
}

// ---------------------------------------------------------------------------
// Windowed causal attention. One block per (segment, head).
// ---------------------------------------------------------------------------
__global__ void attn_kernel(const int* __restrict__ cu, int T, float* __restrict__ attn_out)
{
    extern __shared__ float sm[];
    float* Qs = sm;                       // [64][80]
    float* Ks = Qs + WIN * HD;            // [64][81]
    float* Vs = Ks + WIN * 81;            // [64][80]
    float* S  = Vs + WIN * HD;            // [64][64]

    int seg = blockIdx.x;
    int h   = blockIdx.y;
    int st  = cu[seg];
    int en  = cu[seg + 1];
    int L   = en - st;
    if (L > WIN) L = WIN;
    int tid = threadIdx.x;  // 128
    const float scale = 0.11180339887498948f;

    const float* Qg = g_q + (size_t)h * T * HD;
    const float* Kg = g_k + (size_t)h * T * HD;
    const float* Vg = g_v + (size_t)h * T * HD;

    for (int e = tid; e < WIN * HD; e += blockDim.x) {
        int r = e / HD, d = e % HD;
        float qv = 0.f, kv = 0.f, vv = 0.f;
        if (r < L) {
            size_t g = (size_t)(st + r) * HD + d;
            qv = Qg[g]; kv = Kg[g]; vv = Vg[g];
        }
        Qs[r * HD + d] = qv;
        Ks[r * 81 + d] = kv;
        Vs[r * HD + d] = vv;
    }
    __syncthreads();

    for (int e = tid; e < WIN * WIN; e += blockDim.x) {
        int r = e >> 6, c = e & 63;
        if (r < L && c <= r) {
            float acc = 0.f;
            #pragma unroll 8
            for (int d = 0; d < HD; ++d)
                acc += Qs[r * HD + d] * Ks[c * 81 + d];
            S[e] = acc * scale;
        }
    }
    __syncthreads();

    if (tid < WIN) {
        int r = tid;
        if (r < L) {
            float m = -1e30f;
            for (int c = 0; c <= r; ++c) m = fmaxf(m, S[r * WIN + c]);
            float sum = 0.f;
            for (int c = 0; c <= r; ++c) {
                float e = expf(S[r * WIN + c] - m);
                S[r * WIN + c] = e;
                sum += e;
            }
            float inv = 1.f / sum;
            for (int c = 0; c < WIN; ++c)
                S[r * WIN + c] = (c <= r) ? S[r * WIN + c] * inv : 0.f;
        } else {
            for (int c = 0; c < WIN; ++c) S[r * WIN + c] = 0.f;
        }
    }
    __syncthreads();

    for (int e = tid; e < WIN * HD; e += blockDim.x) {
        int r = e / HD, d = e % HD;
        if (r >= L) continue;
        float acc = 0.f;
        #pragma unroll 8
        for (int c = 0; c < WIN; ++c)
            acc += S[r * WIN + c] * Vs[c * HD + d];
        attn_out[(size_t)(st + r) * D_MODEL + h * HD + d] = acc;
    }
}

// ---------------------------------------------------------------------------
// launch
// ---------------------------------------------------------------------------
extern "C" void kernel_launch(void* const* d_in, const int* in_sizes, int n_in,
                              void* d_out, int out_size)
{
    const float* x    = (const float*)d_in[0];
    const float* rope = (const float*)d_in[1];
    const int*   cu   = (const int*)  d_in[2];
    const float* Wqkv = (const float*)d_in[3];
    const float* bqkv = (const float*)d_in[4];
    const float* Wo   = (const float*)d_in[5];
    const float* bo   = (const float*)d_in[6];
    float* out = (float*)d_out;

    const int T = in_sizes[0] / D_MODEL;   // 4096
    const int nseg = in_sizes[2] - 1;      // 64

    float *qkv_p, *att_p;
    __nv_bfloat16 *xh, *xl, *wqh, *wql, *woh, *wol, *ah, *al;
    cudaGetSymbolAddress((void**)&qkv_p, g_qkv);
    cudaGetSymbolAddress((void**)&att_p, g_att);
    cudaGetSymbolAddress((void**)&xh, g_xh);
    cudaGetSymbolAddress((void**)&xl, g_xl);
    cudaGetSymbolAddress((void**)&wqh, g_wqh);
    cudaGetSymbolAddress((void**)&wql, g_wql);
    cudaGetSymbolAddress((void**)&woh, g_woh);
    cudaGetSymbolAddress((void**)&wol, g_wol);
    cudaGetSymbolAddress((void**)&ah, g_ah);
    cudaGetSymbolAddress((void**)&al, g_al);

    const int gemm_smem = NSTAGE * STAGE_B;   // 122880
    cudaFuncSetAttribute(gemm_bf16x3,
                         cudaFuncAttributeMaxDynamicSharedMemorySize, gemm_smem);

    // 0) operand prep
    {
        int n = T * D_MODEL;
        split_bf16_kernel<<<(n + 255) / 256, 256>>>(x, xh, xl, n);
        dim3 blk(32, 8);
        transpose_split_kernel<<<dim3(E3 / 32, KDIM / 32), blk>>>(Wqkv, wqh, wql, KDIM, E3);
        transpose_split_kernel<<<dim3(D_MODEL / 32, KDIM / 32), blk>>>(Wo, woh, wol, KDIM, D_MODEL);
    }

    // 1) QKV projection (tensor cores): [T,1280] x [1280,3840] + bqkv
    {
        dim3 grid(E3 / GBN, T / GBM);
        gemm_bf16x3<<<grid, 256, gemm_smem>>>(T, E3, KDIM, xh, xl, wqh, wql, bqkv, qkv_p);
    }

    // 2) RoPE + head split
    {
        int total = T * NHEAD * HD;
        rope_split_kernel<<<(total + 255) / 256, 256>>>(rope, T);
    }

    // 3) windowed attention
    {
        int smem = (WIN * HD + WIN * 81 + WIN * HD + WIN * WIN) * (int)sizeof(float);
        cudaFuncSetAttribute(attn_kernel, cudaFuncAttributeMaxDynamicSharedMemorySize, smem);
        dim3 grid(nseg, NHEAD);
        attn_kernel<<<grid, 128, smem>>>(cu, T, att_p);
    }

    // 3b) split attention output to bf16 hi/lo
    {
        int n = T * D_MODEL;
        split_bf16_kernel<<<(n + 255) / 256, 256>>>(att_p, ah, al, n);
    }

    // 4) output projection (tensor cores): [T,1280] x [1280,1280] + bo
    {
        dim3 grid(D_MODEL / GBN, T / GBM);
        gemm_bf16x3<<<grid, 256, gemm_smem>>>(T, D_MODEL, KDIM, ah, al, woh, wol, bo, out);
    }
}

// round 6
// speedup vs baseline: 2.5326x; 1.2772x over previous
#include <cuda_runtime.h>
#include <cuda_bf16.h>
#include <math.h>
#include <stdint.h>

// Problem constants (fixed by setup_inputs)
#define T_MAX 4096
#define D_MODEL 1280
#define NHEAD 16
#define HD 80
#define E3 (3 * D_MODEL)   // 3840
#define WIN 64
#define KDIM 1280

// ---------------------------------------------------------------------------
// Scratch (device globals; no allocations allowed)
// ---------------------------------------------------------------------------
__device__ float g_qkv[T_MAX * E3];

__device__ __nv_bfloat16 g_xh[T_MAX * D_MODEL];
__device__ __nv_bfloat16 g_xl[T_MAX * D_MODEL];
__device__ __nv_bfloat16 g_wqh[E3 * D_MODEL];     // Wqkv^T [N,K]
__device__ __nv_bfloat16 g_wql[E3 * D_MODEL];
__device__ __nv_bfloat16 g_woh[D_MODEL * D_MODEL];
__device__ __nv_bfloat16 g_wol[D_MODEL * D_MODEL];
__device__ __nv_bfloat16 g_ah[T_MAX * D_MODEL];   // attn out split hi/lo
__device__ __nv_bfloat16 g_al[T_MAX * D_MODEL];

// ---------------------------------------------------------------------------
// Low-level helpers (baseline PTX, safe for compute_100)
// ---------------------------------------------------------------------------
__device__ __forceinline__ uint32_t smem_u32(const void* p) {
    uint32_t a;
    asm("{ .reg .u64 t; cvta.to.shared.u64 t, %1; cvt.u32.u64 %0, t; }"
        : "=r"(a) : "l"(p));
    return a;
}

__device__ __forceinline__ void cp_async16(uint32_t dst, const void* src) {
    asm volatile("cp.async.cg.shared.global [%0], [%1], 16;" :: "r"(dst), "l"(src));
}

__device__ __forceinline__ void ldm_x4(uint32_t* r, uint32_t addr) {
    asm volatile("ldmatrix.sync.aligned.m8n8.x4.shared.b16 {%0,%1,%2,%3}, [%4];"
                 : "=r"(r[0]), "=r"(r[1]), "=r"(r[2]), "=r"(r[3]) : "r"(addr));
}

__device__ __forceinline__ void mma_bf16(float* d, const uint32_t* a, const uint32_t* b) {
    asm volatile(
        "mma.sync.aligned.m16n8k16.row.col.f32.bf16.bf16.f32 "
        "{%0,%1,%2,%3}, {%4,%5,%6,%7}, {%8,%9}, {%0,%1,%2,%3};"
        : "+f"(d[0]), "+f"(d[1]), "+f"(d[2]), "+f"(d[3])
        : "r"(a[0]), "r"(a[1]), "r"(a[2]), "r"(a[3]), "r"(b[0]), "r"(b[1]));
}

// ---------------------------------------------------------------------------
// GEMM: C[M,N] = (Ah+Al)[M,K] @ (Bh+Bl)[N,K]^T + bias[N]  (fp32 accum)
// mma.sync bf16, 128x128 tile, BK=32, 2-stage cp.async, 2 CTAs/SM.
// smem row stride = 40 bf16 (80B): conflict-free ldmatrix (phase 5r mod 8).
// ---------------------------------------------------------------------------
#define GBM 128
#define GBN 128
#define GBK 32
#define ROWP 40                        // padded row length (elements)
#define TILE_B (128 * ROWP * 2)        // 10240 bytes per sub-tile
#define STAGE_B (4 * TILE_B)           // Ah, Al, Bh, Bl = 40960 bytes
#define NSTAGE 2

__global__ void __launch_bounds__(256, 2)
gemm_bf16x3(int M, int N, int K,
            const __nv_bfloat16* __restrict__ Ah, const __nv_bfloat16* __restrict__ Al,
            const __nv_bfloat16* __restrict__ Bh, const __nv_bfloat16* __restrict__ Bl,
            const float* __restrict__ bias, float* __restrict__ C)
{
    extern __shared__ __align__(128) char dsm[];
    const uint32_t sbase = smem_u32(dsm);

    const int tid  = threadIdx.x;
    const int wid  = tid >> 5;
    const int lane = tid & 31;
    const int warp_m = wid >> 2;       // 0..1
    const int warp_n = wid & 3;        // 0..3
    const int m0 = blockIdx.y * GBM;
    const int n0 = blockIdx.x * GBN;

    const int NC = K / GBK;            // 40 chunks? no: 1280/32 = 40

    // ---- stage loader -----------------------------------------------------
    auto load_stage = [&](int cidx) {
        const uint32_t sb = sbase + (uint32_t)(cidx & 1) * STAGE_B;
        const int k0 = cidx * GBK;
        const __nv_bfloat16* srcs[4] = {
            Ah + (size_t)m0 * K + k0,
            Al + (size_t)m0 * K + k0,
            Bh + (size_t)n0 * K + k0,
            Bl + (size_t)n0 * K + k0
        };
        #pragma unroll
        for (int t = 0; t < 4; ++t) {
            const __nv_bfloat16* sp = srcs[t];
            #pragma unroll
            for (int j = 0; j < 2; ++j) {
                int e   = tid + j * 256;       // 0..511
                int row = e >> 2;              // 0..127
                int ch  = e & 3;               // 16B chunk within 64B row
                cp_async16(sb + (uint32_t)t * TILE_B + (uint32_t)(row * 80 + ch * 16),
                           sp + (size_t)row * K + ch * 8);
            }
        }
        asm volatile("cp.async.commit_group;");
    };

    float acc[4][4][4];
    #pragma unroll
    for (int i = 0; i < 4; ++i)
        #pragma unroll
        for (int j = 0; j < 4; ++j)
            #pragma unroll
            for (int q = 0; q < 4; ++q) acc[i][j][q] = 0.f;

    load_stage(0);
    load_stage(1);

    // ldmatrix lane addressing (fixed per thread)
    const int a_row = lane & 15;
    const int a_kof = (lane >> 4) * 8;
    const int b_row = (lane & 7) + ((lane >> 4) << 3);
    const int b_kof = ((lane >> 3) & 1) * 8;

    for (int c = 0; c < NC; ++c) {
        if (c + 1 < NC) {
            asm volatile("cp.async.wait_group 1;");
        } else {
            asm volatile("cp.async.wait_group 0;");
        }
        __syncthreads();

        const uint32_t sb = sbase + (uint32_t)(c & 1) * STAGE_B;

        #pragma unroll
        for (int kk = 0; kk < 2; ++kk) {
            const int k0 = kk * 16;
            // phase 1: aH, bH, bL live (32 frag regs)
            {
                uint32_t aH[4][4], bH[2][4], bL[2][4];
                #pragma unroll
                for (int ma = 0; ma < 4; ++ma) {
                    int row = warp_m * 64 + ma * 16 + a_row;
                    uint32_t off = (uint32_t)(row * ROWP + k0 + a_kof) * 2;
                    ldm_x4(aH[ma], sb + 0 * TILE_B + off);
                }
                #pragma unroll
                for (int np = 0; np < 2; ++np) {
                    int row = warp_n * 32 + np * 16 + b_row;
                    uint32_t off = (uint32_t)(row * ROWP + k0 + b_kof) * 2;
                    ldm_x4(bH[np], sb + 2 * TILE_B + off);
                    ldm_x4(bL[np], sb + 3 * TILE_B + off);
                }
                #pragma unroll
                for (int ma = 0; ma < 4; ++ma)
                    #pragma unroll
                    for (int nb = 0; nb < 4; ++nb) {
                        mma_bf16(acc[ma][nb], aH[ma], &bH[nb >> 1][(nb & 1) * 2]);
                        mma_bf16(acc[ma][nb], aH[ma], &bL[nb >> 1][(nb & 1) * 2]);
                    }
                // phase 2: aL replaces aH (dead), bH still live
                uint32_t aL[4][4];
                #pragma unroll
                for (int ma = 0; ma < 4; ++ma) {
                    int row = warp_m * 64 + ma * 16 + a_row;
                    uint32_t off = (uint32_t)(row * ROWP + k0 + a_kof) * 2;
                    ldm_x4(aL[ma], sb + 1 * TILE_B + off);
                }
                #pragma unroll
                for (int ma = 0; ma < 4; ++ma)
                    #pragma unroll
                    for (int nb = 0; nb < 4; ++nb)
                        mma_bf16(acc[ma][nb], aL[ma], &bH[nb >> 1][(nb & 1) * 2]);
            }
        }
        __syncthreads();
        if (c + 2 < NC) load_stage(c + 2);
    }

    // ---- epilogue: direct stores with bias --------------------------------
    const int er = lane >> 2;          // 0..7
    const int ec = (lane & 3) * 2;     // 0,2,4,6
    #pragma unroll
    for (int ma = 0; ma < 4; ++ma) {
        int gr = m0 + warp_m * 64 + ma * 16 + er;
        #pragma unroll
        for (int nb = 0; nb < 4; ++nb) {
            int gc = n0 + warp_n * 32 + nb * 8 + ec;
            float b0 = __ldg(&bias[gc]);
            float b1 = __ldg(&bias[gc + 1]);
            float2 v0 = make_float2(acc[ma][nb][0] + b0, acc[ma][nb][1] + b1);
            float2 v1 = make_float2(acc[ma][nb][2] + b0, acc[ma][nb][3] + b1);
            *(float2*)&C[(size_t)gr * N + gc] = v0;
            *(float2*)&C[(size_t)(gr + 8) * N + gc] = v1;
        }
    }
}

// ---------------------------------------------------------------------------
// Split fp32 -> bf16 hi/lo
// ---------------------------------------------------------------------------
__global__ void split_bf16_kernel(const float* __restrict__ x,
                                  __nv_bfloat16* __restrict__ h,
                                  __nv_bfloat16* __restrict__ l, int n)
{
    int i = blockIdx.x * blockDim.x + threadIdx.x;
    if (i < n) {
        float v = x[i];
        __nv_bfloat16 hi = __float2bfloat16_rn(v);
        h[i] = hi;
        l[i] = __float2bfloat16_rn(v - __bfloat162float(hi));
    }
}

// ---------------------------------------------------------------------------
// Transpose + split: W[K,N] fp32 -> Wt_h, Wt_l [N,K] bf16
// ---------------------------------------------------------------------------
__global__ void transpose_split_kernel(const float* __restrict__ W,
                                       __nv_bfloat16* __restrict__ th,
                                       __nv_bfloat16* __restrict__ tl,
                                       int Kd, int Nd)
{
    __shared__ float tile[32][33];
    int kb = blockIdx.y * 32, nb = blockIdx.x * 32;
    int tx = threadIdx.x, ty = threadIdx.y;    // 32 x 8
    #pragma unroll
    for (int i = 0; i < 32; i += 8)
        tile[ty + i][tx] = W[(size_t)(kb + ty + i) * Nd + nb + tx];
    __syncthreads();
    #pragma unroll
    for (int i = 0; i < 32; i += 8) {
        float v = tile[tx][ty + i];
        __nv_bfloat16 hi = __float2bfloat16_rn(v);
        size_t o = (size_t)(nb + ty + i) * Kd + kb + tx;
        th[o] = hi;
        tl[o] = __float2bfloat16_rn(v - __bfloat162float(hi));
    }
}

// ---------------------------------------------------------------------------
// Fused RoPE + windowed causal attention + bf16 split epilogue.
// One block (128 threads) per (segment, head). Register-tiled matmuls.
// smem strides: Qs/Ks 81, Vs 80, S 65 (conflict-free per access pattern).
// ---------------------------------------------------------------------------
#define QKS 81
#define SST 65

__global__ void __launch_bounds__(128, 2)
attn_fused_kernel(const int* __restrict__ cu, const float* __restrict__ rope,
                  int T,
                  __nv_bfloat16* __restrict__ ah, __nv_bfloat16* __restrict__ al)
{
    extern __shared__ float sm[];
    float* Qs = sm;                        // [64][81]
    float* Ks = Qs + WIN * QKS;            // [64][81]
    float* Vs = Ks + WIN * QKS;            // [64][80]
    float* S  = Vs + WIN * HD;             // [64][65]

    const int seg = blockIdx.x;
    const int h   = blockIdx.y;
    const int st  = cu[seg];
    int L = cu[seg + 1] - st;
    if (L > WIN) L = WIN;
    const int tid = threadIdx.x;
    const float scale = 0.11180339887498948f;   // 1/sqrt(80)

    // ---- load + RoPE ------------------------------------------------------
    // q/k rotate pairs (j, j+40); v plain copy.
    for (int e = tid; e < WIN * 40; e += 128) {
        int r = e / 40, j = e % 40;
        float q0 = 0.f, q1 = 0.f, k0 = 0.f, k1 = 0.f;
        if (r < L) {
            size_t base = (size_t)(st + r) * E3 + (size_t)h * HD;
            float ang = rope[(st + r) * 40 + j];
            float c = cosf(ang), s = sinf(ang);
            float qr = g_qkv[base + j],        qi = g_qkv[base + 40 + j];
            float kr = g_qkv[base + D_MODEL + j], ki = g_qkv[base + D_MODEL + 40 + j];
            q0 = qr * c - qi * s;  q1 = qr * s + qi * c;
            k0 = kr * c - ki * s;  k1 = kr * s + ki * c;
        }
        Qs[r * QKS + j]      = q0;
        Qs[r * QKS + 40 + j] = q1;
        Ks[r * QKS + j]      = k0;
        Ks[r * QKS + 40 + j] = k1;
    }
    for (int e = tid; e < WIN * HD; e += 128) {
        int r = e / HD, d = e % HD;
        float vv = 0.f;
        if (r < L)
            vv = g_qkv[(size_t)(st + r) * E3 + (size_t)h * HD + 2 * D_MODEL + d];
        Vs[r * HD + d] = vv;
    }
    __syncthreads();

    // ---- S = Q K^T * scale  (4x8 register tile, strided cols) -------------
    {
        const int rg = tid >> 3;           // 0..15 -> rows rg*4..rg*4+3
        const int cg = tid & 7;            // cols cg + 8*j
        float accS[4][8];
        #pragma unroll
        for (int i = 0; i < 4; ++i)
            #pragma unroll
            for (int j = 0; j < 8; ++j) accS[i][j] = 0.f;
        for (int d = 0; d < HD; ++d) {
            float qv[4], kv[8];
            #pragma unroll
            for (int i = 0; i < 4; ++i) qv[i] = Qs[(rg * 4 + i) * QKS + d];
            #pragma unroll
            for (int j = 0; j < 8; ++j) kv[j] = Ks[(cg + 8 * j) * QKS + d];
            #pragma unroll
            for (int i = 0; i < 4; ++i)
                #pragma unroll
                for (int j = 0; j < 8; ++j)
                    accS[i][j] += qv[i] * kv[j];
        }
        #pragma unroll
        for (int i = 0; i < 4; ++i)
            #pragma unroll
            for (int j = 0; j < 8; ++j)
                S[(rg * 4 + i) * SST + cg + 8 * j] = accS[i][j] * scale;
    }
    __syncthreads();

    // ---- softmax: 2 threads per row ---------------------------------------
    {
        const int r = tid >> 1;
        const int p = tid & 1;
        if (r < L) {
            float* row = &S[r * SST];
            const int c0 = p * 32;
            float m = -1e30f;
            #pragma unroll 8
            for (int c = c0; c < c0 + 32; ++c)
                if (c <= r) m = fmaxf(m, row[c]);
            m = fmaxf(m, __shfl_xor_sync(0xffffffffu, m, 1));
            float sum = 0.f;
            #pragma unroll 8
            for (int c = c0; c < c0 + 32; ++c) {
                float e = (c <= r) ? __expf(row[c] - m) : 0.f;
                row[c] = e;
                sum += e;
            }
            sum += __shfl_xor_sync(0xffffffffu, sum, 1);
            float inv = 1.f / sum;
            #pragma unroll 8
            for (int c = c0; c < c0 + 32; ++c) row[c] *= inv;
        }
    }
    __syncthreads();

    // ---- O = P V  (4x10 register tile) + bf16 hi/lo epilogue --------------
    {
        const int rg = tid >> 3;           // rows rg*4..rg*4+3
        const int dg = tid & 7;            // d cols dg*10..dg*10+9
        float accO[4][10];
        #pragma unroll
        for (int i = 0; i < 4; ++i)
            #pragma unroll
            for (int u = 0; u < 10; ++u) accO[i][u] = 0.f;
        const int cmax = rg * 4 + 3;       // causal: rows in group see c <= row
        for (int c = 0; c <= cmax; ++c) {
            float sv[4], vv[10];
            #pragma unroll
            for (int i = 0; i < 4; ++i) sv[i] = S[(rg * 4 + i) * SST + c];
            #pragma unroll
            for (int u = 0; u < 10; ++u) vv[u] = Vs[c * HD + dg * 10 + u];
            #pragma unroll
            for (int i = 0; i < 4; ++i)
                #pragma unroll
                for (int u = 0; u < 10; ++u)
                    accO[i][u] += sv[i] * vv[u];
        }
        #pragma unroll
        for (int i = 0; i < 4; ++i) {
            int r = rg * 4 + i;
            if (r < L) {
                size_t o = (size_t)(st + r) * D_MODEL + (size_t)h * HD + dg * 10;
                #pragma unroll
                for (int u = 0; u < 10; ++u) {
                    float v = accO[i][u];
                    __nv_bfloat16 hi = __float2bfloat16_rn(v);
                    ah[o + u] = hi;
                    al[o + u] = __float2bfloat16_rn(v - __bfloat162float(hi));
                }
            }
        }
    }
}

// ---------------------------------------------------------------------------
// launch
// ---------------------------------------------------------------------------
extern "C" void kernel_launch(void* const* d_in, const int* in_sizes, int n_in,
                              void* d_out, int out_size)
{
    const float* x    = (const float*)d_in[0];
    const float* rope = (const float*)d_in[1];
    const int*   cu   = (const int*)  d_in[2];
    const float* Wqkv = (const float*)d_in[3];
    const float* bqkv = (const float*)d_in[4];
    const float* Wo   = (const float*)d_in[5];
    const float* bo   = (const float*)d_in[6];
    float* out = (float*)d_out;

    const int T = in_sizes[0] / D_MODEL;   // 4096
    const int nseg = in_sizes[2] - 1;      // 64

    float* qkv_p;
    __nv_bfloat16 *xh, *xl, *wqh, *wql, *woh, *wol, *ah, *al;
    cudaGetSymbolAddress((void**)&qkv_p, g_qkv);
    cudaGetSymbolAddress((void**)&xh, g_xh);
    cudaGetSymbolAddress((void**)&xl, g_xl);
    cudaGetSymbolAddress((void**)&wqh, g_wqh);
    cudaGetSymbolAddress((void**)&wql, g_wql);
    cudaGetSymbolAddress((void**)&woh, g_woh);
    cudaGetSymbolAddress((void**)&wol, g_wol);
    cudaGetSymbolAddress((void**)&ah, g_ah);
    cudaGetSymbolAddress((void**)&al, g_al);

    const int gemm_smem = NSTAGE * STAGE_B;   // 81920
    cudaFuncSetAttribute(gemm_bf16x3,
                         cudaFuncAttributeMaxDynamicSharedMemorySize, gemm_smem);

    // 0) operand prep
    {
        int n = T * D_MODEL;
        split_bf16_kernel<<<(n + 255) / 256, 256>>>(x, xh, xl, n);
        dim3 blk(32, 8);
        transpose_split_kernel<<<dim3(E3 / 32, KDIM / 32), blk>>>(Wqkv, wqh, wql, KDIM, E3);
        transpose_split_kernel<<<dim3(D_MODEL / 32, KDIM / 32), blk>>>(Wo, woh, wol, KDIM, D_MODEL);
    }

    // 1) QKV projection: [T,1280] x [1280,3840] + bqkv
    {
        dim3 grid(E3 / GBN, T / GBM);
        gemm_bf16x3<<<grid, 256, gemm_smem>>>(T, E3, KDIM, xh, xl, wqh, wql, bqkv, qkv_p);
    }

    // 2) fused RoPE + windowed attention -> bf16 hi/lo
    {
        int smem = (2 * WIN * QKS + WIN * HD + WIN * SST) * (int)sizeof(float); // 78592
        cudaFuncSetAttribute(attn_fused_kernel,
                             cudaFuncAttributeMaxDynamicSharedMemorySize, smem);
        dim3 grid(nseg, NHEAD);
        attn_fused_kernel<<<grid, 128, smem>>>(cu, rope, T, ah, al);
    }

    // 3) output projection: [T,1280] x [1280,1280] + bo
    {
        dim3 grid(D_MODEL / GBN, T / GBM);
        gemm_bf16x3<<<grid, 256, gemm_smem>>>(T, D_MODEL, KDIM, ah, al, woh, wol, bo, out);
    }
}

// round 7
// speedup vs baseline: 2.7734x; 1.0951x over previous
#include <cuda_runtime.h>
#include <cuda_bf16.h>
#include <math.h>
#include <stdint.h>

// Problem constants (fixed by setup_inputs)
#define T_MAX 4096
#define D_MODEL 1280
#define NHEAD 16
#define HD 80
#define E3 (3 * D_MODEL)   // 3840
#define WIN 64
#define KDIM 1280

// ---------------------------------------------------------------------------
// Scratch (device globals; no allocations allowed)
// ---------------------------------------------------------------------------
__device__ float g_qkv[T_MAX * E3];

__device__ __nv_bfloat16 g_xh[T_MAX * D_MODEL];
__device__ __nv_bfloat16 g_xl[T_MAX * D_MODEL];
__device__ __nv_bfloat16 g_wqh[E3 * D_MODEL];     // Wqkv^T [N,K]
__device__ __nv_bfloat16 g_wql[E3 * D_MODEL];
__device__ __nv_bfloat16 g_woh[D_MODEL * D_MODEL];
__device__ __nv_bfloat16 g_wol[D_MODEL * D_MODEL];
__device__ __nv_bfloat16 g_ah[T_MAX * D_MODEL];   // attn out split hi/lo
__device__ __nv_bfloat16 g_al[T_MAX * D_MODEL];

// ---------------------------------------------------------------------------
// Low-level helpers (baseline PTX, safe for compute_100)
// ---------------------------------------------------------------------------
__device__ __forceinline__ uint32_t smem_u32(const void* p) {
    uint32_t a;
    asm("{ .reg .u64 t; cvta.to.shared.u64 t, %1; cvt.u32.u64 %0, t; }"
        : "=r"(a) : "l"(p));
    return a;
}

__device__ __forceinline__ void cp_async16(uint32_t dst, const void* src) {
    asm volatile("cp.async.cg.shared.global [%0], [%1], 16;" :: "r"(dst), "l"(src));
}

__device__ __forceinline__ void ldm_x4(uint32_t* r, uint32_t addr) {
    asm volatile("ldmatrix.sync.aligned.m8n8.x4.shared.b16 {%0,%1,%2,%3}, [%4];"
                 : "=r"(r[0]), "=r"(r[1]), "=r"(r[2]), "=r"(r[3]) : "r"(addr));
}

__device__ __forceinline__ void mma_bf16(float* d, const uint32_t* a, const uint32_t* b) {
    asm volatile(
        "mma.sync.aligned.m16n8k16.row.col.f32.bf16.bf16.f32 "
        "{%0,%1,%2,%3}, {%4,%5,%6,%7}, {%8,%9}, {%0,%1,%2,%3};"
        : "+f"(d[0]), "+f"(d[1]), "+f"(d[2]), "+f"(d[3])
        : "r"(a[0]), "r"(a[1]), "r"(a[2]), "r"(a[3]), "r"(b[0]), "r"(b[1]));
}

// ---------------------------------------------------------------------------
// GEMM: C[M,N] = (Ah+Al)[M,K] @ (Bh+Bl)[N,K]^T + bias[N]  (fp32 accum)
// mma.sync bf16, 128x128 tile, BK=32, 2-stage cp.async, 2 CTAs/SM.
// smem row stride = 40 bf16 (80B): conflict-free ldmatrix (phase 5r mod 8).
// ---------------------------------------------------------------------------
#define GBM 128
#define GBN 128
#define GBK 32
#define ROWP 40                        // padded row length (elements)
#define TILE_B (128 * ROWP * 2)        // 10240 bytes per sub-tile
#define STAGE_B (4 * TILE_B)           // Ah, Al, Bh, Bl = 40960 bytes
#define NSTAGE 2

__global__ void __launch_bounds__(256, 2)
gemm_bf16x3(int M, int N, int K,
            const __nv_bfloat16* __restrict__ Ah, const __nv_bfloat16* __restrict__ Al,
            const __nv_bfloat16* __restrict__ Bh, const __nv_bfloat16* __restrict__ Bl,
            const float* __restrict__ bias, float* __restrict__ C)
{
    extern __shared__ __align__(128) char dsm[];
    const uint32_t sbase = smem_u32(dsm);

    const int tid  = threadIdx.x;
    const int wid  = tid >> 5;
    const int lane = tid & 31;
    const int warp_m = wid >> 2;       // 0..1
    const int warp_n = wid & 3;        // 0..3
    const int m0 = blockIdx.y * GBM;
    const int n0 = blockIdx.x * GBN;

    const int NC = K / GBK;            // 40

    // ---- stage loader -----------------------------------------------------
    auto load_stage = [&](int cidx) {
        const uint32_t sb = sbase + (uint32_t)(cidx & 1) * STAGE_B;
        const int k0 = cidx * GBK;
        const __nv_bfloat16* srcs[4] = {
            Ah + (size_t)m0 * K + k0,
            Al + (size_t)m0 * K + k0,
            Bh + (size_t)n0 * K + k0,
            Bl + (size_t)n0 * K + k0
        };
        #pragma unroll
        for (int t = 0; t < 4; ++t) {
            const __nv_bfloat16* sp = srcs[t];
            #pragma unroll
            for (int j = 0; j < 2; ++j) {
                int e   = tid + j * 256;       // 0..511
                int row = e >> 2;              // 0..127
                int ch  = e & 3;               // 16B chunk within 64B row
                cp_async16(sb + (uint32_t)t * TILE_B + (uint32_t)(row * 80 + ch * 16),
                           sp + (size_t)row * K + ch * 8);
            }
        }
        asm volatile("cp.async.commit_group;");
    };

    float acc[4][4][4];
    #pragma unroll
    for (int i = 0; i < 4; ++i)
        #pragma unroll
        for (int j = 0; j < 4; ++j)
            #pragma unroll
            for (int q = 0; q < 4; ++q) acc[i][j][q] = 0.f;

    load_stage(0);
    load_stage(1);

    // ldmatrix lane addressing (fixed per thread)
    const int a_row = lane & 15;
    const int a_kof = (lane >> 4) * 8;
    const int b_row = (lane & 7) + ((lane >> 4) << 3);
    const int b_kof = ((lane >> 3) & 1) * 8;

    for (int c = 0; c < NC; ++c) {
        if (c + 1 < NC) {
            asm volatile("cp.async.wait_group 1;");
        } else {
            asm volatile("cp.async.wait_group 0;");
        }
        __syncthreads();

        const uint32_t sb = sbase + (uint32_t)(c & 1) * STAGE_B;

        #pragma unroll
        for (int kk = 0; kk < 2; ++kk) {
            const int k0 = kk * 16;
            // phase 1: aH, bH, bL live (32 frag regs)
            {
                uint32_t aH[4][4], bH[2][4], bL[2][4];
                #pragma unroll
                for (int ma = 0; ma < 4; ++ma) {
                    int row = warp_m * 64 + ma * 16 + a_row;
                    uint32_t off = (uint32_t)(row * ROWP + k0 + a_kof) * 2;
                    ldm_x4(aH[ma], sb + 0 * TILE_B + off);
                }
                #pragma unroll
                for (int np = 0; np < 2; ++np) {
                    int row = warp_n * 32 + np * 16 + b_row;
                    uint32_t off = (uint32_t)(row * ROWP + k0 + b_kof) * 2;
                    ldm_x4(bH[np], sb + 2 * TILE_B + off);
                    ldm_x4(bL[np], sb + 3 * TILE_B + off);
                }
                #pragma unroll
                for (int ma = 0; ma < 4; ++ma)
                    #pragma unroll
                    for (int nb = 0; nb < 4; ++nb) {
                        mma_bf16(acc[ma][nb], aH[ma], &bH[nb >> 1][(nb & 1) * 2]);
                        mma_bf16(acc[ma][nb], aH[ma], &bL[nb >> 1][(nb & 1) * 2]);
                    }
                // phase 2: aL replaces aH (dead), bH still live
                uint32_t aL[4][4];
                #pragma unroll
                for (int ma = 0; ma < 4; ++ma) {
                    int row = warp_m * 64 + ma * 16 + a_row;
                    uint32_t off = (uint32_t)(row * ROWP + k0 + a_kof) * 2;
                    ldm_x4(aL[ma], sb + 1 * TILE_B + off);
                }
                #pragma unroll
                for (int ma = 0; ma < 4; ++ma)
                    #pragma unroll
                    for (int nb = 0; nb < 4; ++nb)
                        mma_bf16(acc[ma][nb], aL[ma], &bH[nb >> 1][(nb & 1) * 2]);
            }
        }
        __syncthreads();
        if (c + 2 < NC) load_stage(c + 2);
    }

    // ---- epilogue: direct stores with bias --------------------------------
    const int er = lane >> 2;          // 0..7
    const int ec = (lane & 3) * 2;     // 0,2,4,6
    #pragma unroll
    for (int ma = 0; ma < 4; ++ma) {
        int gr = m0 + warp_m * 64 + ma * 16 + er;
        #pragma unroll
        for (int nb = 0; nb < 4; ++nb) {
            int gc = n0 + warp_n * 32 + nb * 8 + ec;
            float b0 = __ldg(&bias[gc]);
            float b1 = __ldg(&bias[gc + 1]);
            float2 v0 = make_float2(acc[ma][nb][0] + b0, acc[ma][nb][1] + b1);
            float2 v1 = make_float2(acc[ma][nb][2] + b0, acc[ma][nb][3] + b1);
            *(float2*)&C[(size_t)gr * N + gc] = v0;
            *(float2*)&C[(size_t)(gr + 8) * N + gc] = v1;
        }
    }
}

// ---------------------------------------------------------------------------
// Split fp32 -> bf16 hi/lo
// ---------------------------------------------------------------------------
__global__ void split_bf16_kernel(const float* __restrict__ x,
                                  __nv_bfloat16* __restrict__ h,
                                  __nv_bfloat16* __restrict__ l, int n)
{
    int i = blockIdx.x * blockDim.x + threadIdx.x;
    if (i < n) {
        float v = x[i];
        __nv_bfloat16 hi = __float2bfloat16_rn(v);
        h[i] = hi;
        l[i] = __float2bfloat16_rn(v - __bfloat162float(hi));
    }
}

// ---------------------------------------------------------------------------
// Transpose + split: W[K,N] fp32 -> Wt_h, Wt_l [N,K] bf16
// ---------------------------------------------------------------------------
__global__ void transpose_split_kernel(const float* __restrict__ W,
                                       __nv_bfloat16* __restrict__ th,
                                       __nv_bfloat16* __restrict__ tl,
                                       int Kd, int Nd)
{
    __shared__ float tile[32][33];
    int kb = blockIdx.y * 32, nb = blockIdx.x * 32;
    int tx = threadIdx.x, ty = threadIdx.y;    // 32 x 8
    #pragma unroll
    for (int i = 0; i < 32; i += 8)
        tile[ty + i][tx] = W[(size_t)(kb + ty + i) * Nd + nb + tx];
    __syncthreads();
    #pragma unroll
    for (int i = 0; i < 32; i += 8) {
        float v = tile[tx][ty + i];
        __nv_bfloat16 hi = __float2bfloat16_rn(v);
        size_t o = (size_t)(nb + ty + i) * Kd + kb + tx;
        th[o] = hi;
        tl[o] = __float2bfloat16_rn(v - __bfloat162float(hi));
    }
}

// ---------------------------------------------------------------------------
// Fused RoPE + windowed causal attention + bf16 split epilogue.
// One block (256 threads) per (segment, head). Register-tiled matmuls.
// smem strides: Qs/Ks 81, Vs 80, S 65 (conflict-free per access pattern).
// ---------------------------------------------------------------------------
#define QKS 81
#define SST 65

__global__ void __launch_bounds__(256, 2)
attn_fused_kernel(const int* __restrict__ cu, const float* __restrict__ rope,
                  int T,
                  __nv_bfloat16* __restrict__ ah, __nv_bfloat16* __restrict__ al)
{
    extern __shared__ float sm[];
    float* Qs = sm;                        // [64][81]
    float* Ks = Qs + WIN * QKS;            // [64][81]
    float* Vs = Ks + WIN * QKS;            // [64][80]
    float* S  = Vs + WIN * HD;             // [64][65]

    const int seg = blockIdx.x;
    const int h   = blockIdx.y;
    const int st  = cu[seg];
    int L = cu[seg + 1] - st;
    if (L > WIN) L = WIN;
    const int tid = threadIdx.x;
    const float scale = 0.11180339887498948f;   // 1/sqrt(80)

    // ---- load + RoPE ------------------------------------------------------
    for (int e = tid; e < WIN * 40; e += 256) {
        int r = e / 40, j = e % 40;
        float q0 = 0.f, q1 = 0.f, k0 = 0.f, k1 = 0.f;
        if (r < L) {
            size_t base = (size_t)(st + r) * E3 + (size_t)h * HD;
            float ang = rope[(st + r) * 40 + j];
            float c = cosf(ang), s = sinf(ang);
            float qr = g_qkv[base + j],           qi = g_qkv[base + 40 + j];
            float kr = g_qkv[base + D_MODEL + j], ki = g_qkv[base + D_MODEL + 40 + j];
            q0 = qr * c - qi * s;  q1 = qr * s + qi * c;
            k0 = kr * c - ki * s;  k1 = kr * s + ki * c;
        }
        Qs[r * QKS + j]      = q0;
        Qs[r * QKS + 40 + j] = q1;
        Ks[r * QKS + j]      = k0;
        Ks[r * QKS + 40 + j] = k1;
    }
    for (int e = tid; e < WIN * HD; e += 256) {
        int r = e / HD, d = e % HD;
        float vv = 0.f;
        if (r < L)
            vv = g_qkv[(size_t)(st + r) * E3 + (size_t)h * HD + 2 * D_MODEL + d];
        Vs[r * HD + d] = vv;
    }
    __syncthreads();

    // ---- S = Q K^T * scale  (2x8 register tile, strided cols) -------------
    {
        const int rg = tid >> 3;           // 0..31 -> rows rg*2, rg*2+1
        const int cg = tid & 7;            // cols cg + 8*j
        float accS[2][8];
        #pragma unroll
        for (int i = 0; i < 2; ++i)
            #pragma unroll
            for (int j = 0; j < 8; ++j) accS[i][j] = 0.f;
        for (int d = 0; d < HD; ++d) {
            float qv[2], kv[8];
            #pragma unroll
            for (int i = 0; i < 2; ++i) qv[i] = Qs[(rg * 2 + i) * QKS + d];
            #pragma unroll
            for (int j = 0; j < 8; ++j) kv[j] = Ks[(cg + 8 * j) * QKS + d];
            #pragma unroll
            for (int i = 0; i < 2; ++i)
                #pragma unroll
                for (int j = 0; j < 8; ++j)
                    accS[i][j] += qv[i] * kv[j];
        }
        #pragma unroll
        for (int i = 0; i < 2; ++i)
            #pragma unroll
            for (int j = 0; j < 8; ++j)
                S[(rg * 2 + i) * SST + cg + 8 * j] = accS[i][j] * scale;
    }
    __syncthreads();

    // ---- softmax: 4 threads per row ---------------------------------------
    {
        const int r = tid >> 2;            // 0..63
        const int p = tid & 3;             // 16 cols each
        if (r < L) {
            float* row = &S[r * SST];
            const int c0 = p * 16;
            float m = -1e30f;
            #pragma unroll 4
            for (int c = c0; c < c0 + 16; ++c)
                if (c <= r) m = fmaxf(m, row[c]);
            m = fmaxf(m, __shfl_xor_sync(0xffffffffu, m, 1));
            m = fmaxf(m, __shfl_xor_sync(0xffffffffu, m, 2));
            float sum = 0.f;
            #pragma unroll 4
            for (int c = c0; c < c0 + 16; ++c) {
                float e = (c <= r) ? __expf(row[c] - m) : 0.f;
                row[c] = e;
                sum += e;
            }
            sum += __shfl_xor_sync(0xffffffffu, sum, 1);
            sum += __shfl_xor_sync(0xffffffffu, sum, 2);
            float inv = 1.f / sum;
            #pragma unroll 4
            for (int c = c0; c < c0 + 16; ++c) row[c] *= inv;
        }
    }
    __syncthreads();

    // ---- O = P V  (2x10 register tile) + bf16 hi/lo epilogue --------------
    {
        const int rg = tid >> 3;           // rows rg*2, rg*2+1
        const int dg = tid & 7;            // d cols dg*10..dg*10+9
        float accO[2][10];
        #pragma unroll
        for (int i = 0; i < 2; ++i)
            #pragma unroll
            for (int u = 0; u < 10; ++u) accO[i][u] = 0.f;
        const int cmax = rg * 2 + 1;       // causal: rows see c <= row
        for (int c = 0; c <= cmax; ++c) {
            float sv[2], vv[10];
            #pragma unroll
            for (int i = 0; i < 2; ++i) sv[i] = S[(rg * 2 + i) * SST + c];
            #pragma unroll
            for (int u = 0; u < 10; ++u) vv[u] = Vs[c * HD + dg * 10 + u];
            #pragma unroll
            for (int i = 0; i < 2; ++i)
                #pragma unroll
                for (int u = 0; u < 10; ++u)
                    accO[i][u] += sv[i] * vv[u];
        }
        #pragma unroll
        for (int i = 0; i < 2; ++i) {
            int r = rg * 2 + i;
            if (r < L) {
                size_t o = (size_t)(st + r) * D_MODEL + (size_t)h * HD + dg * 10;
                #pragma unroll
                for (int u = 0; u < 10; ++u) {
                    float v = accO[i][u];
                    __nv_bfloat16 hi = __float2bfloat16_rn(v);
                    ah[o + u] = hi;
                    al[o + u] = __float2bfloat16_rn(v - __bfloat162float(hi));
                }
            }
        }
    }
}

// ---------------------------------------------------------------------------
// launch
// ---------------------------------------------------------------------------
extern "C" void kernel_launch(void* const* d_in, const int* in_sizes, int n_in,
                              void* d_out, int out_size)
{
    const float* x    = (const float*)d_in[0];
    const float* rope = (const float*)d_in[1];
    const int*   cu   = (const int*)  d_in[2];
    const float* Wqkv = (const float*)d_in[3];
    const float* bqkv = (const float*)d_in[4];
    const float* Wo   = (const float*)d_in[5];
    const float* bo   = (const float*)d_in[6];
    float* out = (float*)d_out;

    const int T = in_sizes[0] / D_MODEL;   // 4096
    const int nseg = in_sizes[2] - 1;      // 64

    float* qkv_p;
    __nv_bfloat16 *xh, *xl, *wqh, *wql, *woh, *wol, *ah, *al;
    cudaGetSymbolAddress((void**)&qkv_p, g_qkv);
    cudaGetSymbolAddress((void**)&xh, g_xh);
    cudaGetSymbolAddress((void**)&xl, g_xl);
    cudaGetSymbolAddress((void**)&wqh, g_wqh);
    cudaGetSymbolAddress((void**)&wql, g_wql);
    cudaGetSymbolAddress((void**)&woh, g_woh);
    cudaGetSymbolAddress((void**)&wol, g_wol);
    cudaGetSymbolAddress((void**)&ah, g_ah);
    cudaGetSymbolAddress((void**)&al, g_al);

    const int gemm_smem = NSTAGE * STAGE_B;   // 81920
    cudaFuncSetAttribute(gemm_bf16x3,
                         cudaFuncAttributeMaxDynamicSharedMemorySize, gemm_smem);

    // 0) operand prep
    {
        int n = T * D_MODEL;
        split_bf16_kernel<<<(n + 255) / 256, 256>>>(x, xh, xl, n);
        dim3 blk(32, 8);
        transpose_split_kernel<<<dim3(E3 / 32, KDIM / 32), blk>>>(Wqkv, wqh, wql, KDIM, E3);
        transpose_split_kernel<<<dim3(D_MODEL / 32, KDIM / 32), blk>>>(Wo, woh, wol, KDIM, D_MODEL);
    }

    // 1) QKV projection: [T,1280] x [1280,3840] + bqkv
    {
        dim3 grid(E3 / GBN, T / GBM);
        gemm_bf16x3<<<grid, 256, gemm_smem>>>(T, E3, KDIM, xh, xl, wqh, wql, bqkv, qkv_p);
    }

    // 2) fused RoPE + windowed attention -> bf16 hi/lo
    {
        int smem = (2 * WIN * QKS + WIN * HD + WIN * SST) * (int)sizeof(float); // 78592
        cudaFuncSetAttribute(attn_fused_kernel,
                             cudaFuncAttributeMaxDynamicSharedMemorySize, smem);
        dim3 grid(nseg, NHEAD);
        attn_fused_kernel<<<grid, 256, smem>>>(cu, rope, T, ah, al);
    }

    // 3) output projection: [T,1280] x [1280,1280] + bo
    {
        dim3 grid(D_MODEL / GBN, T / GBM);
        gemm_bf16x3<<<grid, 256, gemm_smem>>>(T, D_MODEL, KDIM, ah, al, woh, wol, bo, out);
    }
}

// round 8
// speedup vs baseline: 3.0139x; 1.0867x over previous
#include <cuda_runtime.h>
#include <cuda_bf16.h>
#include <math.h>
#include <stdint.h>

// Problem constants (fixed by setup_inputs)
#define T_MAX 4096
#define D_MODEL 1280
#define NHEAD 16
#define HD 80
#define E3 (3 * D_MODEL)   // 3840
#define WIN 64
#define KDIM 1280

// ---------------------------------------------------------------------------
// Scratch (device globals; no allocations allowed)
// ---------------------------------------------------------------------------
__device__ float g_qkv[T_MAX * E3];

__device__ __nv_bfloat16 g_xh[T_MAX * D_MODEL];
__device__ __nv_bfloat16 g_xl[T_MAX * D_MODEL];
__device__ __nv_bfloat16 g_wqh[E3 * D_MODEL];     // Wqkv^T [N,K]
__device__ __nv_bfloat16 g_wql[E3 * D_MODEL];
__device__ __nv_bfloat16 g_woh[D_MODEL * D_MODEL];
__device__ __nv_bfloat16 g_wol[D_MODEL * D_MODEL];
__device__ __nv_bfloat16 g_ah[T_MAX * D_MODEL];   // attn out split hi/lo
__device__ __nv_bfloat16 g_al[T_MAX * D_MODEL];

// ---------------------------------------------------------------------------
// Low-level helpers (baseline PTX, safe for compute_100)
// ---------------------------------------------------------------------------
__device__ __forceinline__ uint32_t smem_u32(const void* p) {
    uint32_t a;
    asm("{ .reg .u64 t; cvta.to.shared.u64 t, %1; cvt.u32.u64 %0, t; }"
        : "=r"(a) : "l"(p));
    return a;
}

__device__ __forceinline__ void cp_async16(uint32_t dst, const void* src) {
    asm volatile("cp.async.cg.shared.global [%0], [%1], 16;" :: "r"(dst), "l"(src));
}

__device__ __forceinline__ void ldm_x4(uint32_t* r, uint32_t addr) {
    asm volatile("ldmatrix.sync.aligned.m8n8.x4.shared.b16 {%0,%1,%2,%3}, [%4];"
                 : "=r"(r[0]), "=r"(r[1]), "=r"(r[2]), "=r"(r[3]) : "r"(addr));
}

__device__ __forceinline__ void mma_bf16(float* d, const uint32_t* a, const uint32_t* b) {
    asm volatile(
        "mma.sync.aligned.m16n8k16.row.col.f32.bf16.bf16.f32 "
        "{%0,%1,%2,%3}, {%4,%5,%6,%7}, {%8,%9}, {%0,%1,%2,%3};"
        : "+f"(d[0]), "+f"(d[1]), "+f"(d[2]), "+f"(d[3])
        : "r"(a[0]), "r"(a[1]), "r"(a[2]), "r"(a[3]), "r"(b[0]), "r"(b[1]));
}

// ---------------------------------------------------------------------------
// GEMM: C[M,N] = (Ah+Al)[M,K] @ (Bh+Bl)[N,K]^T + bias[N]  (fp32 accum)
// mma.sync bf16, 128x128 tile, BK=32, 3-stage cp.async, 1 sync/chunk,
// XOR-swizzled 64B rows (no padding): chunk ^= (row>>1)&3.
// 2 CTAs/SM (96 KB smem + 128 regs each).
// ---------------------------------------------------------------------------
#define GBM 128
#define GBN 128
#define GBK 32
#define TILE_B (128 * 64)              // 8192 bytes per sub-tile (64B rows)
#define STAGE_B (4 * TILE_B)           // Ah, Al, Bh, Bl = 32768 bytes
#define NSTAGE 3

__device__ __forceinline__ uint32_t sw_off(int row, int ch) {
    return (uint32_t)(row * 64) + ((uint32_t)(ch ^ ((row >> 1) & 3)) << 4);
}

__global__ void __launch_bounds__(256, 2)
gemm_bf16x3(int M, int N, int K,
            const __nv_bfloat16* __restrict__ Ah, const __nv_bfloat16* __restrict__ Al,
            const __nv_bfloat16* __restrict__ Bh, const __nv_bfloat16* __restrict__ Bl,
            const float* __restrict__ bias, float* __restrict__ C)
{
    extern __shared__ __align__(128) char dsm[];
    const uint32_t sbase = smem_u32(dsm);

    const int tid  = threadIdx.x;
    const int wid  = tid >> 5;
    const int lane = tid & 31;
    const int warp_m = wid >> 2;       // 0..1
    const int warp_n = wid & 3;        // 0..3
    const int m0 = blockIdx.y * GBM;
    const int n0 = blockIdx.x * GBN;

    const int NC = K / GBK;            // 40

    // ---- stage loader (swizzled) ------------------------------------------
    auto load_stage = [&](int cidx) {
        const uint32_t sb = sbase + (uint32_t)(cidx % NSTAGE) * STAGE_B;
        const int k0 = cidx * GBK;
        const __nv_bfloat16* srcs[4] = {
            Ah + (size_t)m0 * K + k0,
            Al + (size_t)m0 * K + k0,
            Bh + (size_t)n0 * K + k0,
            Bl + (size_t)n0 * K + k0
        };
        #pragma unroll
        for (int t = 0; t < 4; ++t) {
            const __nv_bfloat16* sp = srcs[t];
            #pragma unroll
            for (int j = 0; j < 2; ++j) {
                int e   = tid + j * 256;       // 0..511
                int row = e >> 2;              // 0..127
                int ch  = e & 3;               // 16B chunk in 64B row
                cp_async16(sb + (uint32_t)t * TILE_B + sw_off(row, ch),
                           sp + (size_t)row * K + ch * 8);
            }
        }
        asm volatile("cp.async.commit_group;");
    };

    float acc[4][4][4];
    #pragma unroll
    for (int i = 0; i < 4; ++i)
        #pragma unroll
        for (int j = 0; j < 4; ++j)
            #pragma unroll
            for (int q = 0; q < 4; ++q) acc[i][j][q] = 0.f;

    load_stage(0);
    load_stage(1);

    // ldmatrix lane addressing (fixed per thread)
    const int a_row = lane & 15;
    const int a_kch = (lane >> 4);             // +0/+1 chunk
    const int b_row = (lane & 7) + ((lane >> 4) << 3);
    const int b_kch = ((lane >> 3) & 1);

    for (int c = 0; c < NC; ++c) {
        if (c + 1 < NC) {
            asm volatile("cp.async.wait_group 1;");
        } else {
            asm volatile("cp.async.wait_group 0;");
        }
        __syncthreads();
        if (c + 2 < NC) load_stage(c + 2);     // overlaps compute below

        const uint32_t sb = sbase + (uint32_t)(c % NSTAGE) * STAGE_B;

        #pragma unroll
        for (int kk = 0; kk < 2; ++kk) {
            const int kc = kk * 2;             // base chunk (k0 = kk*16)
            // phase 1: aH, bH, bL live
            {
                uint32_t aH[4][4], bH[2][4], bL[2][4];
                #pragma unroll
                for (int ma = 0; ma < 4; ++ma) {
                    int row = warp_m * 64 + ma * 16 + a_row;
                    uint32_t off = sw_off(row, kc + a_kch);
                    ldm_x4(aH[ma], sb + 0 * TILE_B + off);
                }
                #pragma unroll
                for (int np = 0; np < 2; ++np) {
                    int row = warp_n * 32 + np * 16 + b_row;
                    uint32_t off = sw_off(row, kc + b_kch);
                    ldm_x4(bH[np], sb + 2 * TILE_B + off);
                    ldm_x4(bL[np], sb + 3 * TILE_B + off);
                }
                #pragma unroll
                for (int ma = 0; ma < 4; ++ma)
                    #pragma unroll
                    for (int nb = 0; nb < 4; ++nb) {
                        mma_bf16(acc[ma][nb], aH[ma], &bH[nb >> 1][(nb & 1) * 2]);
                        mma_bf16(acc[ma][nb], aH[ma], &bL[nb >> 1][(nb & 1) * 2]);
                    }
                // phase 2: aL replaces aH (dead), bH still live
                uint32_t aL[4][4];
                #pragma unroll
                for (int ma = 0; ma < 4; ++ma) {
                    int row = warp_m * 64 + ma * 16 + a_row;
                    uint32_t off = sw_off(row, kc + a_kch);
                    ldm_x4(aL[ma], sb + 1 * TILE_B + off);
                }
                #pragma unroll
                for (int ma = 0; ma < 4; ++ma)
                    #pragma unroll
                    for (int nb = 0; nb < 4; ++nb)
                        mma_bf16(acc[ma][nb], aL[ma], &bH[nb >> 1][(nb & 1) * 2]);
            }
        }
        // no trailing sync: next iter's syncthreads protects buffer reuse
    }

    // ---- epilogue: direct stores with bias --------------------------------
    const int er = lane >> 2;          // 0..7
    const int ec = (lane & 3) * 2;     // 0,2,4,6
    #pragma unroll
    for (int ma = 0; ma < 4; ++ma) {
        int gr = m0 + warp_m * 64 + ma * 16 + er;
        #pragma unroll
        for (int nb = 0; nb < 4; ++nb) {
            int gc = n0 + warp_n * 32 + nb * 8 + ec;
            float b0 = __ldg(&bias[gc]);
            float b1 = __ldg(&bias[gc + 1]);
            float2 v0 = make_float2(acc[ma][nb][0] + b0, acc[ma][nb][1] + b1);
            float2 v1 = make_float2(acc[ma][nb][2] + b0, acc[ma][nb][3] + b1);
            *(float2*)&C[(size_t)gr * N + gc] = v0;
            *(float2*)&C[(size_t)(gr + 8) * N + gc] = v1;
        }
    }
}

// ---------------------------------------------------------------------------
// Split fp32 -> bf16 hi/lo
// ---------------------------------------------------------------------------
__global__ void split_bf16_kernel(const float* __restrict__ x,
                                  __nv_bfloat16* __restrict__ h,
                                  __nv_bfloat16* __restrict__ l, int n)
{
    int i = blockIdx.x * blockDim.x + threadIdx.x;
    if (i < n) {
        float v = x[i];
        __nv_bfloat16 hi = __float2bfloat16_rn(v);
        h[i] = hi;
        l[i] = __float2bfloat16_rn(v - __bfloat162float(hi));
    }
}

// ---------------------------------------------------------------------------
// Transpose + split: W[K,N] fp32 -> Wt_h, Wt_l [N,K] bf16
// ---------------------------------------------------------------------------
__global__ void transpose_split_kernel(const float* __restrict__ W,
                                       __nv_bfloat16* __restrict__ th,
                                       __nv_bfloat16* __restrict__ tl,
                                       int Kd, int Nd)
{
    __shared__ float tile[32][33];
    int kb = blockIdx.y * 32, nb = blockIdx.x * 32;
    int tx = threadIdx.x, ty = threadIdx.y;    // 32 x 8
    #pragma unroll
    for (int i = 0; i < 32; i += 8)
        tile[ty + i][tx] = W[(size_t)(kb + ty + i) * Nd + nb + tx];
    __syncthreads();
    #pragma unroll
    for (int i = 0; i < 32; i += 8) {
        float v = tile[tx][ty + i];
        __nv_bfloat16 hi = __float2bfloat16_rn(v);
        size_t o = (size_t)(nb + ty + i) * Kd + kb + tx;
        th[o] = hi;
        tl[o] = __float2bfloat16_rn(v - __bfloat162float(hi));
    }
}

// ---------------------------------------------------------------------------
// Fused RoPE + windowed causal attention + bf16 split epilogue.
// One block (256 threads) per (segment, head). Register-tiled matmuls.
// smem strides: Qs/Ks 81, Vs 80, S 65 (conflict-free per access pattern).
// ---------------------------------------------------------------------------
#define QKS 81
#define SST 65

__global__ void __launch_bounds__(256, 2)
attn_fused_kernel(const int* __restrict__ cu, const float* __restrict__ rope,
                  int T,
                  __nv_bfloat16* __restrict__ ah, __nv_bfloat16* __restrict__ al)
{
    extern __shared__ float sm[];
    float* Qs = sm;                        // [64][81]
    float* Ks = Qs + WIN * QKS;            // [64][81]
    float* Vs = Ks + WIN * QKS;            // [64][80]
    float* S  = Vs + WIN * HD;             // [64][65]

    const int seg = blockIdx.x;
    const int h   = blockIdx.y;
    const int st  = cu[seg];
    int L = cu[seg + 1] - st;
    if (L > WIN) L = WIN;
    const int tid = threadIdx.x;
    const float scale = 0.11180339887498948f;   // 1/sqrt(80)

    // ---- load + RoPE ------------------------------------------------------
    for (int e = tid; e < WIN * 40; e += 256) {
        int r = e / 40, j = e % 40;
        float q0 = 0.f, q1 = 0.f, k0 = 0.f, k1 = 0.f;
        if (r < L) {
            size_t base = (size_t)(st + r) * E3 + (size_t)h * HD;
            float ang = rope[(st + r) * 40 + j];
            float c = cosf(ang), s = sinf(ang);
            float qr = g_qkv[base + j],           qi = g_qkv[base + 40 + j];
            float kr = g_qkv[base + D_MODEL + j], ki = g_qkv[base + D_MODEL + 40 + j];
            q0 = qr * c - qi * s;  q1 = qr * s + qi * c;
            k0 = kr * c - ki * s;  k1 = kr * s + ki * c;
        }
        Qs[r * QKS + j]      = q0;
        Qs[r * QKS + 40 + j] = q1;
        Ks[r * QKS + j]      = k0;
        Ks[r * QKS + 40 + j] = k1;
    }
    for (int e = tid; e < WIN * HD; e += 256) {
        int r = e / HD, d = e % HD;
        float vv = 0.f;
        if (r < L)
            vv = g_qkv[(size_t)(st + r) * E3 + (size_t)h * HD + 2 * D_MODEL + d];
        Vs[r * HD + d] = vv;
    }
    __syncthreads();

    // ---- S = Q K^T * scale  (2x8 register tile, strided cols) -------------
    {
        const int rg = tid >> 3;           // 0..31 -> rows rg*2, rg*2+1
        const int cg = tid & 7;            // cols cg + 8*j
        float accS[2][8];
        #pragma unroll
        for (int i = 0; i < 2; ++i)
            #pragma unroll
            for (int j = 0; j < 8; ++j) accS[i][j] = 0.f;
        for (int d = 0; d < HD; ++d) {
            float qv[2], kv[8];
            #pragma unroll
            for (int i = 0; i < 2; ++i) qv[i] = Qs[(rg * 2 + i) * QKS + d];
            #pragma unroll
            for (int j = 0; j < 8; ++j) kv[j] = Ks[(cg + 8 * j) * QKS + d];
            #pragma unroll
            for (int i = 0; i < 2; ++i)
                #pragma unroll
                for (int j = 0; j < 8; ++j)
                    accS[i][j] += qv[i] * kv[j];
        }
        #pragma unroll
        for (int i = 0; i < 2; ++i)
            #pragma unroll
            for (int j = 0; j < 8; ++j)
                S[(rg * 2 + i) * SST + cg + 8 * j] = accS[i][j] * scale;
    }
    __syncthreads();

    // ---- softmax: 4 threads per row ---------------------------------------
    {
        const int r = tid >> 2;            // 0..63
        const int p = tid & 3;             // 16 cols each
        if (r < L) {
            float* row = &S[r * SST];
            const int c0 = p * 16;
            float m = -1e30f;
            #pragma unroll 4
            for (int c = c0; c < c0 + 16; ++c)
                if (c <= r) m = fmaxf(m, row[c]);
            m = fmaxf(m, __shfl_xor_sync(0xffffffffu, m, 1));
            m = fmaxf(m, __shfl_xor_sync(0xffffffffu, m, 2));
            float sum = 0.f;
            #pragma unroll 4
            for (int c = c0; c < c0 + 16; ++c) {
                float e = (c <= r) ? __expf(row[c] - m) : 0.f;
                row[c] = e;
                sum += e;
            }
            sum += __shfl_xor_sync(0xffffffffu, sum, 1);
            sum += __shfl_xor_sync(0xffffffffu, sum, 2);
            float inv = 1.f / sum;
            #pragma unroll 4
            for (int c = c0; c < c0 + 16; ++c) row[c] *= inv;
        }
    }
    __syncthreads();

    // ---- O = P V  (2x10 register tile) + bf16 hi/lo epilogue --------------
    {
        const int rg = tid >> 3;           // rows rg*2, rg*2+1
        const int dg = tid & 7;            // d cols dg*10..dg*10+9
        float accO[2][10];
        #pragma unroll
        for (int i = 0; i < 2; ++i)
            #pragma unroll
            for (int u = 0; u < 10; ++u) accO[i][u] = 0.f;
        const int cmax = rg * 2 + 1;       // causal: rows see c <= row
        for (int c = 0; c <= cmax; ++c) {
            float sv[2], vv[10];
            #pragma unroll
            for (int i = 0; i < 2; ++i) sv[i] = S[(rg * 2 + i) * SST + c];
            #pragma unroll
            for (int u = 0; u < 10; ++u) vv[u] = Vs[c * HD + dg * 10 + u];
            #pragma unroll
            for (int i = 0; i < 2; ++i)
                #pragma unroll
                for (int u = 0; u < 10; ++u)
                    accO[i][u] += sv[i] * vv[u];
        }
        #pragma unroll
        for (int i = 0; i < 2; ++i) {
            int r = rg * 2 + i;
            if (r < L) {
                size_t o = (size_t)(st + r) * D_MODEL + (size_t)h * HD + dg * 10;
                #pragma unroll
                for (int u = 0; u < 10; ++u) {
                    float v = accO[i][u];
                    __nv_bfloat16 hi = __float2bfloat16_rn(v);
                    ah[o + u] = hi;
                    al[o + u] = __float2bfloat16_rn(v - __bfloat162float(hi));
                }
            }
        }
    }
}

// ---------------------------------------------------------------------------
// launch
// ---------------------------------------------------------------------------
extern "C" void kernel_launch(void* const* d_in, const int* in_sizes, int n_in,
                              void* d_out, int out_size)
{
    const float* x    = (const float*)d_in[0];
    const float* rope = (const float*)d_in[1];
    const int*   cu   = (const int*)  d_in[2];
    const float* Wqkv = (const float*)d_in[3];
    const float* bqkv = (const float*)d_in[4];
    const float* Wo   = (const float*)d_in[5];
    const float* bo   = (const float*)d_in[6];
    float* out = (float*)d_out;

    const int T = in_sizes[0] / D_MODEL;   // 4096
    const int nseg = in_sizes[2] - 1;      // 64

    float* qkv_p;
    __nv_bfloat16 *xh, *xl, *wqh, *wql, *woh, *wol, *ah, *al;
    cudaGetSymbolAddress((void**)&qkv_p, g_qkv);
    cudaGetSymbolAddress((void**)&xh, g_xh);
    cudaGetSymbolAddress((void**)&xl, g_xl);
    cudaGetSymbolAddress((void**)&wqh, g_wqh);
    cudaGetSymbolAddress((void**)&wql, g_wql);
    cudaGetSymbolAddress((void**)&woh, g_woh);
    cudaGetSymbolAddress((void**)&wol, g_wol);
    cudaGetSymbolAddress((void**)&ah, g_ah);
    cudaGetSymbolAddress((void**)&al, g_al);

    const int gemm_smem = NSTAGE * STAGE_B;   // 98304
    cudaFuncSetAttribute(gemm_bf16x3,
                         cudaFuncAttributeMaxDynamicSharedMemorySize, gemm_smem);

    // 0) operand prep
    {
        int n = T * D_MODEL;
        split_bf16_kernel<<<(n + 255) / 256, 256>>>(x, xh, xl, n);
        dim3 blk(32, 8);
        transpose_split_kernel<<<dim3(E3 / 32, KDIM / 32), blk>>>(Wqkv, wqh, wql, KDIM, E3);
        transpose_split_kernel<<<dim3(D_MODEL / 32, KDIM / 32), blk>>>(Wo, woh, wol, KDIM, D_MODEL);
    }

    // 1) QKV projection: [T,1280] x [1280,3840] + bqkv
    {
        dim3 grid(E3 / GBN, T / GBM);
        gemm_bf16x3<<<grid, 256, gemm_smem>>>(T, E3, KDIM, xh, xl, wqh, wql, bqkv, qkv_p);
    }

    // 2) fused RoPE + windowed attention -> bf16 hi/lo
    {
        int smem = (2 * WIN * QKS + WIN * HD + WIN * SST) * (int)sizeof(float); // 78592
        cudaFuncSetAttribute(attn_fused_kernel,
                             cudaFuncAttributeMaxDynamicSharedMemorySize, smem);
        dim3 grid(nseg, NHEAD);
        attn_fused_kernel<<<grid, 256, smem>>>(cu, rope, T, ah, al);
    }

    // 3) output projection: [T,1280] x [1280,1280] + bo
    {
        dim3 grid(D_MODEL / GBN, T / GBM);
        gemm_bf16x3<<<grid, 256, gemm_smem>>>(T, D_MODEL, KDIM, ah, al, woh, wol, bo, out);
    }
}

// round 9
// speedup vs baseline: 3.8973x; 1.2931x over previous
#include <cuda_runtime.h>
#include <cuda_bf16.h>
#include <cuda_fp16.h>
#include <math.h>
#include <stdint.h>

// Problem constants (fixed by setup_inputs)
#define T_MAX 4096
#define D_MODEL 1280
#define NHEAD 16
#define HD 80
#define E3 (3 * D_MODEL)   // 3840
#define WIN 64
#define KDIM 1280

// ---------------------------------------------------------------------------
// Scratch (device globals; no allocations allowed)
// ---------------------------------------------------------------------------
__device__ float g_qkv[T_MAX * E3];

__device__ __half g_xh[T_MAX * D_MODEL];      // x split hi/lo (fp16)
__device__ __half g_xl[T_MAX * D_MODEL];
__device__ __half g_wq[E3 * D_MODEL];         // Wqkv^T [N,K] fp16
__device__ __half g_wo[D_MODEL * D_MODEL];    // Wo^T [N,K] fp16
__device__ __half g_ah[T_MAX * D_MODEL];      // attn out split hi/lo (fp16)
__device__ __half g_al[T_MAX * D_MODEL];

// ---------------------------------------------------------------------------
// Low-level helpers (baseline PTX, safe for compute_100)
// ---------------------------------------------------------------------------
__device__ __forceinline__ uint32_t smem_u32(const void* p) {
    uint32_t a;
    asm("{ .reg .u64 t; cvta.to.shared.u64 t, %1; cvt.u32.u64 %0, t; }"
        : "=r"(a) : "l"(p));
    return a;
}

__device__ __forceinline__ void cp_async16(uint32_t dst, const void* src) {
    asm volatile("cp.async.cg.shared.global [%0], [%1], 16;" :: "r"(dst), "l"(src));
}

__device__ __forceinline__ void ldm_x4(uint32_t* r, uint32_t addr) {
    asm volatile("ldmatrix.sync.aligned.m8n8.x4.shared.b16 {%0,%1,%2,%3}, [%4];"
                 : "=r"(r[0]), "=r"(r[1]), "=r"(r[2]), "=r"(r[3]) : "r"(addr));
}

__device__ __forceinline__ void mma_fp16(float* d, const uint32_t* a, const uint32_t* b) {
    asm volatile(
        "mma.sync.aligned.m16n8k16.row.col.f32.f16.f16.f32 "
        "{%0,%1,%2,%3}, {%4,%5,%6,%7}, {%8,%9}, {%0,%1,%2,%3};"
        : "+f"(d[0]), "+f"(d[1]), "+f"(d[2]), "+f"(d[3])
        : "r"(a[0]), "r"(a[1]), "r"(a[2]), "r"(a[3]), "r"(b[0]), "r"(b[1]));
}

// ---------------------------------------------------------------------------
// GEMM: C[M,N] = (Ah+Al)[M,K] @ B[N,K]^T + bias[N]  (fp32 accum, fp16 ops)
// 2 products: Ah*B + Al*B.  128x128 tile, BK=32, 4-stage cp.async pipeline,
// 1 sync/chunk, XOR-swizzled 64B rows. 2 CTAs/SM (96 KB smem, 128 regs).
// ---------------------------------------------------------------------------
#define GBM 128
#define GBN 128
#define GBK 32
#define TILE_B (128 * 64)              // 8192 bytes per sub-tile (64B rows)
#define STAGE_B (3 * TILE_B)           // Ah, Al, B = 24576 bytes
#define NSTAGE 4

__device__ __forceinline__ uint32_t sw_off(int row, int ch) {
    return (uint32_t)(row * 64) + ((uint32_t)(ch ^ ((row >> 1) & 3)) << 4);
}

__global__ void __launch_bounds__(256, 2)
gemm_fp16x2(int M, int N, int K,
            const __half* __restrict__ Ah, const __half* __restrict__ Al,
            const __half* __restrict__ B,
            const float* __restrict__ bias, float* __restrict__ C)
{
    extern __shared__ __align__(128) char dsm[];
    const uint32_t sbase = smem_u32(dsm);

    const int tid  = threadIdx.x;
    const int wid  = tid >> 5;
    const int lane = tid & 31;
    const int warp_m = wid >> 2;       // 0..1
    const int warp_n = wid & 3;        // 0..3
    const int m0 = blockIdx.y * GBM;
    const int n0 = blockIdx.x * GBN;

    const int NC = K / GBK;            // 40

    // ---- stage loader (swizzled) ------------------------------------------
    auto load_stage = [&](int cidx) {
        const uint32_t sb = sbase + (uint32_t)(cidx % NSTAGE) * STAGE_B;
        const int k0 = cidx * GBK;
        const __half* srcs[3] = {
            Ah + (size_t)m0 * K + k0,
            Al + (size_t)m0 * K + k0,
            B  + (size_t)n0 * K + k0
        };
        #pragma unroll
        for (int t = 0; t < 3; ++t) {
            const __half* sp = srcs[t];
            #pragma unroll
            for (int j = 0; j < 2; ++j) {
                int e   = tid + j * 256;       // 0..511
                int row = e >> 2;              // 0..127
                int ch  = e & 3;               // 16B chunk in 64B row
                cp_async16(sb + (uint32_t)t * TILE_B + sw_off(row, ch),
                           sp + (size_t)row * K + ch * 8);
            }
        }
        asm volatile("cp.async.commit_group;");
    };

    float acc[4][4][4];
    #pragma unroll
    for (int i = 0; i < 4; ++i)
        #pragma unroll
        for (int j = 0; j < 4; ++j)
            #pragma unroll
            for (int q = 0; q < 4; ++q) acc[i][j][q] = 0.f;

    load_stage(0);
    load_stage(1);
    load_stage(2);

    // ldmatrix lane addressing (fixed per thread)
    const int a_row = lane & 15;
    const int a_kch = (lane >> 4);             // +0/+1 chunk
    const int b_row = (lane & 7) + ((lane >> 4) << 3);
    const int b_kch = ((lane >> 3) & 1);

    for (int c = 0; c < NC; ++c) {
        if (c + 2 < NC) {
            asm volatile("cp.async.wait_group 2;");
        } else if (c + 1 < NC) {
            asm volatile("cp.async.wait_group 1;");
        } else {
            asm volatile("cp.async.wait_group 0;");
        }
        __syncthreads();
        if (c + 3 < NC) load_stage(c + 3);     // overlaps compute below

        const uint32_t sb = sbase + (uint32_t)(c % NSTAGE) * STAGE_B;

        #pragma unroll
        for (int kk = 0; kk < 2; ++kk) {
            const int kc = kk * 2;             // base chunk (k0 = kk*16)
            // phase 1: aH + b
            uint32_t aH[4][4], bF[2][4];
            #pragma unroll
            for (int ma = 0; ma < 4; ++ma) {
                int row = warp_m * 64 + ma * 16 + a_row;
                ldm_x4(aH[ma], sb + 0 * TILE_B + sw_off(row, kc + a_kch));
            }
            #pragma unroll
            for (int np = 0; np < 2; ++np) {
                int row = warp_n * 32 + np * 16 + b_row;
                ldm_x4(bF[np], sb + 2 * TILE_B + sw_off(row, kc + b_kch));
            }
            #pragma unroll
            for (int ma = 0; ma < 4; ++ma)
                #pragma unroll
                for (int nb = 0; nb < 4; ++nb)
                    mma_fp16(acc[ma][nb], aH[ma], &bF[nb >> 1][(nb & 1) * 2]);
            // phase 2: aL replaces aH (dead), bF still live
            uint32_t aL[4][4];
            #pragma unroll
            for (int ma = 0; ma < 4; ++ma) {
                int row = warp_m * 64 + ma * 16 + a_row;
                ldm_x4(aL[ma], sb + 1 * TILE_B + sw_off(row, kc + a_kch));
            }
            #pragma unroll
            for (int ma = 0; ma < 4; ++ma)
                #pragma unroll
                for (int nb = 0; nb < 4; ++nb)
                    mma_fp16(acc[ma][nb], aL[ma], &bF[nb >> 1][(nb & 1) * 2]);
        }
        // no trailing sync: next iter's syncthreads protects buffer reuse
    }

    // ---- epilogue: direct stores with bias --------------------------------
    const int er = lane >> 2;          // 0..7
    const int ec = (lane & 3) * 2;     // 0,2,4,6
    #pragma unroll
    for (int ma = 0; ma < 4; ++ma) {
        int gr = m0 + warp_m * 64 + ma * 16 + er;
        #pragma unroll
        for (int nb = 0; nb < 4; ++nb) {
            int gc = n0 + warp_n * 32 + nb * 8 + ec;
            float b0 = __ldg(&bias[gc]);
            float b1 = __ldg(&bias[gc + 1]);
            float2 v0 = make_float2(acc[ma][nb][0] + b0, acc[ma][nb][1] + b1);
            float2 v1 = make_float2(acc[ma][nb][2] + b0, acc[ma][nb][3] + b1);
            *(float2*)&C[(size_t)gr * N + gc] = v0;
            *(float2*)&C[(size_t)(gr + 8) * N + gc] = v1;
        }
    }
}

// ---------------------------------------------------------------------------
// Split fp32 -> fp16 hi/lo
// ---------------------------------------------------------------------------
__global__ void split_f16_kernel(const float* __restrict__ x,
                                 __half* __restrict__ h,
                                 __half* __restrict__ l, int n)
{
    int i = blockIdx.x * blockDim.x + threadIdx.x;
    if (i < n) {
        float v = x[i];
        __half hi = __float2half_rn(v);
        h[i] = hi;
        l[i] = __float2half_rn(v - __half2float(hi));
    }
}

// ---------------------------------------------------------------------------
// Transpose + convert: W[K,N] fp32 -> Wt [N,K] fp16
// ---------------------------------------------------------------------------
__global__ void transpose_f16_kernel(const float* __restrict__ W,
                                     __half* __restrict__ t,
                                     int Kd, int Nd)
{
    __shared__ float tile[32][33];
    int kb = blockIdx.y * 32, nb = blockIdx.x * 32;
    int tx = threadIdx.x, ty = threadIdx.y;    // 32 x 8
    #pragma unroll
    for (int i = 0; i < 32; i += 8)
        tile[ty + i][tx] = W[(size_t)(kb + ty + i) * Nd + nb + tx];
    __syncthreads();
    #pragma unroll
    for (int i = 0; i < 32; i += 8)
        t[(size_t)(nb + ty + i) * Kd + kb + tx] = __float2half_rn(tile[tx][ty + i]);
}

// ---------------------------------------------------------------------------
// Fused RoPE + windowed causal attention + fp16 split epilogue.
// One block (256 threads) per (segment, head). Register-tiled matmuls.
// smem strides: Qs/Ks 81, Vs 80, S 65 (conflict-free per access pattern).
// ---------------------------------------------------------------------------
#define QKS 81
#define SST 65

__global__ void __launch_bounds__(256, 2)
attn_fused_kernel(const int* __restrict__ cu, const float* __restrict__ rope,
                  int T,
                  __half* __restrict__ ah, __half* __restrict__ al)
{
    extern __shared__ float sm[];
    float* Qs = sm;                        // [64][81]
    float* Ks = Qs + WIN * QKS;            // [64][81]
    float* Vs = Ks + WIN * QKS;            // [64][80]
    float* S  = Vs + WIN * HD;             // [64][65]

    const int seg = blockIdx.x;
    const int h   = blockIdx.y;
    const int st  = cu[seg];
    int L = cu[seg + 1] - st;
    if (L > WIN) L = WIN;
    const int tid = threadIdx.x;
    const float scale = 0.11180339887498948f;   // 1/sqrt(80)

    // ---- load + RoPE ------------------------------------------------------
    for (int e = tid; e < WIN * 40; e += 256) {
        int r = e / 40, j = e % 40;
        float q0 = 0.f, q1 = 0.f, k0 = 0.f, k1 = 0.f;
        if (r < L) {
            size_t base = (size_t)(st + r) * E3 + (size_t)h * HD;
            float ang = rope[(st + r) * 40 + j];
            float c = cosf(ang), s = sinf(ang);
            float qr = g_qkv[base + j],           qi = g_qkv[base + 40 + j];
            float kr = g_qkv[base + D_MODEL + j], ki = g_qkv[base + D_MODEL + 40 + j];
            q0 = qr * c - qi * s;  q1 = qr * s + qi * c;
            k0 = kr * c - ki * s;  k1 = kr * s + ki * c;
        }
        Qs[r * QKS + j]      = q0;
        Qs[r * QKS + 40 + j] = q1;
        Ks[r * QKS + j]      = k0;
        Ks[r * QKS + 40 + j] = k1;
    }
    for (int e = tid; e < WIN * HD; e += 256) {
        int r = e / HD, d = e % HD;
        float vv = 0.f;
        if (r < L)
            vv = g_qkv[(size_t)(st + r) * E3 + (size_t)h * HD + 2 * D_MODEL + d];
        Vs[r * HD + d] = vv;
    }
    __syncthreads();

    // ---- S = Q K^T * scale  (2x8 register tile, strided cols) -------------
    {
        const int rg = tid >> 3;           // 0..31 -> rows rg*2, rg*2+1
        const int cg = tid & 7;            // cols cg + 8*j
        float accS[2][8];
        #pragma unroll
        for (int i = 0; i < 2; ++i)
            #pragma unroll
            for (int j = 0; j < 8; ++j) accS[i][j] = 0.f;
        for (int d = 0; d < HD; ++d) {
            float qv[2], kv[8];
            #pragma unroll
            for (int i = 0; i < 2; ++i) qv[i] = Qs[(rg * 2 + i) * QKS + d];
            #pragma unroll
            for (int j = 0; j < 8; ++j) kv[j] = Ks[(cg + 8 * j) * QKS + d];
            #pragma unroll
            for (int i = 0; i < 2; ++i)
                #pragma unroll
                for (int j = 0; j < 8; ++j)
                    accS[i][j] += qv[i] * kv[j];
        }
        #pragma unroll
        for (int i = 0; i < 2; ++i)
            #pragma unroll
            for (int j = 0; j < 8; ++j)
                S[(rg * 2 + i) * SST + cg + 8 * j] = accS[i][j] * scale;
    }
    __syncthreads();

    // ---- softmax: 4 threads per row ---------------------------------------
    {
        const int r = tid >> 2;            // 0..63
        const int p = tid & 3;             // 16 cols each
        if (r < L) {
            float* row = &S[r * SST];
            const int c0 = p * 16;
            float m = -1e30f;
            #pragma unroll 4
            for (int c = c0; c < c0 + 16; ++c)
                if (c <= r) m = fmaxf(m, row[c]);
            m = fmaxf(m, __shfl_xor_sync(0xffffffffu, m, 1));
            m = fmaxf(m, __shfl_xor_sync(0xffffffffu, m, 2));
            float sum = 0.f;
            #pragma unroll 4
            for (int c = c0; c < c0 + 16; ++c) {
                float e = (c <= r) ? __expf(row[c] - m) : 0.f;
                row[c] = e;
                sum += e;
            }
            sum += __shfl_xor_sync(0xffffffffu, sum, 1);
            sum += __shfl_xor_sync(0xffffffffu, sum, 2);
            float inv = 1.f / sum;
            #pragma unroll 4
            for (int c = c0; c < c0 + 16; ++c) row[c] *= inv;
        }
    }
    __syncthreads();

    // ---- O = P V  (2x10 register tile) + fp16 hi/lo epilogue --------------
    {
        const int rg = tid >> 3;           // rows rg*2, rg*2+1
        const int dg = tid & 7;            // d cols dg*10..dg*10+9
        float accO[2][10];
        #pragma unroll
        for (int i = 0; i < 2; ++i)
            #pragma unroll
            for (int u = 0; u < 10; ++u) accO[i][u] = 0.f;
        const int cmax = rg * 2 + 1;       // causal: rows see c <= row
        for (int c = 0; c <= cmax; ++c) {
            float sv[2], vv[10];
            #pragma unroll
            for (int i = 0; i < 2; ++i) sv[i] = S[(rg * 2 + i) * SST + c];
            #pragma unroll
            for (int u = 0; u < 10; ++u) vv[u] = Vs[c * HD + dg * 10 + u];
            #pragma unroll
            for (int i = 0; i < 2; ++i)
                #pragma unroll
                for (int u = 0; u < 10; ++u)
                    accO[i][u] += sv[i] * vv[u];
        }
        #pragma unroll
        for (int i = 0; i < 2; ++i) {
            int r = rg * 2 + i;
            if (r < L) {
                size_t o = (size_t)(st + r) * D_MODEL + (size_t)h * HD + dg * 10;
                #pragma unroll
                for (int u = 0; u < 10; ++u) {
                    float v = accO[i][u];
                    __half hi = __float2half_rn(v);
                    ah[o + u] = hi;
                    al[o + u] = __float2half_rn(v - __half2float(hi));
                }
            }
        }
    }
}

// ---------------------------------------------------------------------------
// launch
// ---------------------------------------------------------------------------
extern "C" void kernel_launch(void* const* d_in, const int* in_sizes, int n_in,
                              void* d_out, int out_size)
{
    const float* x    = (const float*)d_in[0];
    const float* rope = (const float*)d_in[1];
    const int*   cu   = (const int*)  d_in[2];
    const float* Wqkv = (const float*)d_in[3];
    const float* bqkv = (const float*)d_in[4];
    const float* Wo   = (const float*)d_in[5];
    const float* bo   = (const float*)d_in[6];
    float* out = (float*)d_out;

    const int T = in_sizes[0] / D_MODEL;   // 4096
    const int nseg = in_sizes[2] - 1;      // 64

    float* qkv_p;
    __half *xh, *xl, *wq, *wo, *ah, *al;
    cudaGetSymbolAddress((void**)&qkv_p, g_qkv);
    cudaGetSymbolAddress((void**)&xh, g_xh);
    cudaGetSymbolAddress((void**)&xl, g_xl);
    cudaGetSymbolAddress((void**)&wq, g_wq);
    cudaGetSymbolAddress((void**)&wo, g_wo);
    cudaGetSymbolAddress((void**)&ah, g_ah);
    cudaGetSymbolAddress((void**)&al, g_al);

    const int gemm_smem = NSTAGE * STAGE_B;   // 98304
    cudaFuncSetAttribute(gemm_fp16x2,
                         cudaFuncAttributeMaxDynamicSharedMemorySize, gemm_smem);

    // 0) operand prep
    {
        int n = T * D_MODEL;
        split_f16_kernel<<<(n + 255) / 256, 256>>>(x, xh, xl, n);
        dim3 blk(32, 8);
        transpose_f16_kernel<<<dim3(E3 / 32, KDIM / 32), blk>>>(Wqkv, wq, KDIM, E3);
        transpose_f16_kernel<<<dim3(D_MODEL / 32, KDIM / 32), blk>>>(Wo, wo, KDIM, D_MODEL);
    }

    // 1) QKV projection: [T,1280] x [1280,3840] + bqkv
    {
        dim3 grid(E3 / GBN, T / GBM);
        gemm_fp16x2<<<grid, 256, gemm_smem>>>(T, E3, KDIM, xh, xl, wq, bqkv, qkv_p);
    }

    // 2) fused RoPE + windowed attention -> fp16 hi/lo
    {
        int smem = (2 * WIN * QKS + WIN * HD + WIN * SST) * (int)sizeof(float); // 78592
        cudaFuncSetAttribute(attn_fused_kernel,
                             cudaFuncAttributeMaxDynamicSharedMemorySize, smem);
        dim3 grid(nseg, NHEAD);
        attn_fused_kernel<<<grid, 256, smem>>>(cu, rope, T, ah, al);
    }

    // 3) output projection: [T,1280] x [1280,1280] + bo
    {
        dim3 grid(D_MODEL / GBN, T / GBM);
        gemm_fp16x2<<<grid, 256, gemm_smem>>>(T, D_MODEL, KDIM, ah, al, wo, bo, out);
    }
}